// round 4
// baseline (speedup 1.0000x reference)
#include <cuda_runtime.h>

#define BATCH 4
#define NL    1024
#define HWN   4096
#define CIN   512
#define CKD   256
#define NH    8
#define DK    32
#define DV    32
#define EPSI  1e-5f
#define QSCALE 0.09016844f   /* (1/16) * log2(e) */
#define ATTN_SMEM 68096

typedef unsigned long long u64;

__device__ __forceinline__ u64 pk(float a, float b) {
    u64 r;
    asm("mov.b64 %0, {%1, %2};" : "=l"(r)
        : "r"(__float_as_uint(a)), "r"(__float_as_uint(b)));
    return r;
}
__device__ __forceinline__ void upk(u64 p, float& a, float& b) {
    unsigned x, y;
    asm("mov.b64 {%0, %1}, %2;" : "=r"(x), "=r"(y) : "l"(p));
    a = __uint_as_float(x); b = __uint_as_float(y);
}
__device__ __forceinline__ u64 fma2(u64 a, u64 b, u64 c) {
    u64 d;
    asm("fma.rn.f32x2 %0, %1, %2, %3;" : "=l"(d) : "l"(a), "l"(b), "l"(c));
    return d;
}
__device__ __forceinline__ u64 add2(u64 a, u64 b) {
    u64 d;
    asm("add.rn.f32x2 %0, %1, %2;" : "=l"(d) : "l"(a), "l"(b));
    return d;
}
__device__ __forceinline__ float ex2(float x) {
    float r; asm("ex2.approx.f32 %0, %1;" : "=f"(r) : "f"(x)); return r;
}

__device__ float g_q[BATCH * NL * CKD];
__device__ float g_k[(size_t)BATCH * CKD * HWN];
__device__ float g_v[(size_t)BATCH * CKD * HWN];
__device__ float g_att[BATCH * NL * CKD];

// ---------------------------------------------------------------------------
// q = l @ Wq^T + bq   (scalar; tiny)
// ---------------------------------------------------------------------------
__global__ __launch_bounds__(256) void gemm_q_kernel(
    const float* __restrict__ L, const float* __restrict__ Wq,
    const float* __restrict__ bq)
{
    __shared__ float As[16][64];
    __shared__ float Bs[16][64];
    const int m0 = blockIdx.y << 6;
    const int c0 = blockIdx.x << 6;
    const int t  = threadIdx.x;
    const int tx = t & 15, ty = t >> 4;
    const int li = t >> 2;
    const int lk = (t & 3) << 2;
    float acc[4][4] = {};
    for (int k0 = 0; k0 < CIN; k0 += 16) {
        float4 a = *(const float4*)&L [(size_t)(m0 + li) * CIN + k0 + lk];
        float4 w = *(const float4*)&Wq[(size_t)(c0 + li) * CIN + k0 + lk];
        __syncthreads();
        As[lk+0][li] = a.x; As[lk+1][li] = a.y; As[lk+2][li] = a.z; As[lk+3][li] = a.w;
        Bs[lk+0][li] = w.x; Bs[lk+1][li] = w.y; Bs[lk+2][li] = w.z; Bs[lk+3][li] = w.w;
        __syncthreads();
        #pragma unroll
        for (int kk = 0; kk < 16; kk++) {
            float4 av = *(const float4*)&As[kk][ty << 2];
            float4 bv = *(const float4*)&Bs[kk][tx << 2];
            float ar[4] = {av.x, av.y, av.z, av.w};
            float br[4] = {bv.x, bv.y, bv.z, bv.w};
            #pragma unroll
            for (int i = 0; i < 4; i++)
                #pragma unroll
                for (int j = 0; j < 4; j++) acc[i][j] += ar[i] * br[j];
        }
    }
    #pragma unroll
    for (int i = 0; i < 4; i++) {
        float4 r = make_float4(acc[i][0] + bq[c0 + (tx << 2) + 0],
                               acc[i][1] + bq[c0 + (tx << 2) + 1],
                               acc[i][2] + bq[c0 + (tx << 2) + 2],
                               acc[i][3] + bq[c0 + (tx << 2) + 3]);
        *(float4*)&g_q[(size_t)(m0 + (ty << 2) + i) * CKD + c0 + (tx << 2)] = r;
    }
}

// ---------------------------------------------------------------------------
// k/v GEMM, f32x2, tile 128n x 64c.  bk dropped (InstanceNorm-invariant).
// ---------------------------------------------------------------------------
__global__ __launch_bounds__(256) void gemm_kv_kernel(
    const float* __restrict__ X, const float* __restrict__ Wk,
    const float* __restrict__ Wv, const float* __restrict__ bv)
{
    __shared__ float As[16][132];   // [k][n 0..127]
    __shared__ float Bs[16][68];    // [k][c 0..63]
    const int b   = blockIdx.z;
    const int isv = blockIdx.y >> 2;
    const int c0  = (blockIdx.y & 3) << 6;
    const int n0  = blockIdx.x << 7;
    const float* W = isv ? Wv : Wk;
    const float* A = X + (size_t)b * HWN * CIN;
    const int t  = threadIdx.x;
    const int tx = t & 15, ty = t >> 4;
    const int ar = t >> 1, ak = (t & 1) << 3;
    const int bc = t >> 2, bk = (t & 3) << 2;
    u64 acc[4][4] = {};   // [c-idx][n-pair]; pairs 0,1 = frag tx*4; 2,3 = frag 64+tx*4
    for (int k0 = 0; k0 < CIN; k0 += 16) {
        float4 x0 = *(const float4*)&A[(size_t)(n0 + ar) * CIN + k0 + ak];
        float4 x1 = *(const float4*)&A[(size_t)(n0 + ar) * CIN + k0 + ak + 4];
        float4 wv = *(const float4*)&W[(size_t)(c0 + bc) * CIN + k0 + bk];
        __syncthreads();
        As[ak+0][ar]=x0.x; As[ak+1][ar]=x0.y; As[ak+2][ar]=x0.z; As[ak+3][ar]=x0.w;
        As[ak+4][ar]=x1.x; As[ak+5][ar]=x1.y; As[ak+6][ar]=x1.z; As[ak+7][ar]=x1.w;
        Bs[bk+0][bc]=wv.x; Bs[bk+1][bc]=wv.y; Bs[bk+2][bc]=wv.z; Bs[bk+3][bc]=wv.w;
        __syncthreads();
        #pragma unroll
        for (int kk = 0; kk < 16; kk++) {
            float4 a0 = *(const float4*)&As[kk][tx << 2];
            float4 a1 = *(const float4*)&As[kk][64 + (tx << 2)];
            u64 np0 = pk(a0.x, a0.y), np1 = pk(a0.z, a0.w);
            u64 np2 = pk(a1.x, a1.y), np3 = pk(a1.z, a1.w);
            float4 cw = *(const float4*)&Bs[kk][ty << 2];
            u64 w0 = pk(cw.x, cw.x), w1 = pk(cw.y, cw.y);
            u64 w2 = pk(cw.z, cw.z), w3 = pk(cw.w, cw.w);
            acc[0][0]=fma2(np0,w0,acc[0][0]); acc[0][1]=fma2(np1,w0,acc[0][1]);
            acc[0][2]=fma2(np2,w0,acc[0][2]); acc[0][3]=fma2(np3,w0,acc[0][3]);
            acc[1][0]=fma2(np0,w1,acc[1][0]); acc[1][1]=fma2(np1,w1,acc[1][1]);
            acc[1][2]=fma2(np2,w1,acc[1][2]); acc[1][3]=fma2(np3,w1,acc[1][3]);
            acc[2][0]=fma2(np0,w2,acc[2][0]); acc[2][1]=fma2(np1,w2,acc[2][1]);
            acc[2][2]=fma2(np2,w2,acc[2][2]); acc[2][3]=fma2(np3,w2,acc[2][3]);
            acc[3][0]=fma2(np0,w3,acc[3][0]); acc[3][1]=fma2(np1,w3,acc[3][1]);
            acc[3][2]=fma2(np2,w3,acc[3][2]); acc[3][3]=fma2(np3,w3,acc[3][3]);
        }
    }
    float* basep = (isv ? g_v : g_k) + (size_t)b * CKD * HWN;
    #pragma unroll
    for (int i = 0; i < 4; i++) {
        const int cc = c0 + (ty << 2) + i;
        const float bias = isv ? bv[cc] : 0.f;
        float r0,r1,r2,r3,r4,r5,r6,r7;
        upk(acc[i][0], r0, r1); upk(acc[i][1], r2, r3);
        upk(acc[i][2], r4, r5); upk(acc[i][3], r6, r7);
        float* rp = basep + (size_t)cc * HWN + n0 + (tx << 2);
        *(float4*)rp        = make_float4(r0+bias, r1+bias, r2+bias, r3+bias);
        *(float4*)(rp + 64) = make_float4(r4+bias, r5+bias, r6+bias, r7+bias);
    }
}

// ---------------------------------------------------------------------------
// InstanceNorm over HW on g_k
// ---------------------------------------------------------------------------
__global__ __launch_bounds__(256) void inorm_k_kernel()
{
    __shared__ float red[16];
    const int row = blockIdx.x;
    float4* p4 = reinterpret_cast<float4*>(g_k + (size_t)row * HWN);
    const int t = threadIdx.x;
    float4 v[4];
    float s = 0.f, sq = 0.f;
    #pragma unroll
    for (int i = 0; i < 4; i++) {
        v[i] = p4[t + 256 * i];
        s  += v[i].x + v[i].y + v[i].z + v[i].w;
        sq += v[i].x * v[i].x + v[i].y * v[i].y + v[i].z * v[i].z + v[i].w * v[i].w;
    }
    #pragma unroll
    for (int off = 16; off; off >>= 1) {
        s  += __shfl_xor_sync(0xffffffffu, s,  off);
        sq += __shfl_xor_sync(0xffffffffu, sq, off);
    }
    if ((t & 31) == 0) { red[t >> 5] = s; red[8 + (t >> 5)] = sq; }
    __syncthreads();
    if (t == 0) {
        float S = 0.f, Q = 0.f;
        #pragma unroll
        for (int i = 0; i < 8; i++) { S += red[i]; Q += red[8 + i]; }
        float mean = S * (1.f / HWN);
        float var  = Q * (1.f / HWN) - mean * mean;
        red[0] = mean;
        red[1] = rsqrtf(var + EPSI);
    }
    __syncthreads();
    const float mean = red[0], rstd = red[1];
    #pragma unroll
    for (int i = 0; i < 4; i++) {
        v[i].x = (v[i].x - mean) * rstd;
        v[i].y = (v[i].y - mean) * rstd;
        v[i].z = (v[i].z - mean) * rstd;
        v[i].w = (v[i].w - mean) * rstd;
        p4[t + 256 * i] = v[i];
    }
}

// ---------------------------------------------------------------------------
// Attention, f32x2: 128 q-rows per block, 64-n chunks.
// Single-pass unnormalized softmax (|logits|<~1), normalize at end.
// ---------------------------------------------------------------------------
__global__ void __launch_bounds__(256, 2) attn_kernel()
{
    extern __shared__ float sm[];
    float (*qsT)[132] = (float(*)[132])sm;            // [d][row]   4224
    float (*ks)[68]   = (float(*)[68])(sm + 4224);    // [d][n]     2176
    float (*vs)[68]   = (float(*)[68])(sm + 6400);    // [dv][n]    2176
    float (*psT)[132] = (float(*)[132])(sm + 8576);   // [n][row]   8448

    const int b = blockIdx.z, h = blockIdx.y, l0 = blockIdx.x << 7;
    const int t = threadIdx.x, tx = t & 15, ty = t >> 4;

    {   // stage Q transposed, pre-scaled by (1/16)*log2e
        const int r = t >> 1, dh = (t & 1) << 4;
        const float* qp = &g_q[(size_t)(b * NL + l0 + r) * CKD + h * DK + dh];
        #pragma unroll
        for (int j = 0; j < 4; j++) {
            float4 qv = *(const float4*)(qp + 4 * j);
            qsT[dh + 4*j + 0][r] = qv.x * QSCALE;
            qsT[dh + 4*j + 1][r] = qv.y * QSCALE;
            qsT[dh + 4*j + 2][r] = qv.z * QSCALE;
            qsT[dh + 4*j + 3][r] = qv.w * QSCALE;
        }
    }

    const float* kbase = g_k + ((size_t)b * CKD + h * DK) * HWN;
    const float* vbase = g_v + ((size_t)b * CKD + h * DV) * HWN;
    const int lr = t >> 3, lc = (t & 7) << 3;

    float4 kr0 = *(const float4*)(kbase + (size_t)lr * HWN + lc);
    float4 kr1 = *(const float4*)(kbase + (size_t)lr * HWN + lc + 4);
    float4 vr0 = *(const float4*)(vbase + (size_t)lr * HWN + lc);
    float4 vr1 = *(const float4*)(vbase + (size_t)lr * HWN + lc + 4);

    u64 O2[4][4] = {};          // [rowpair][dv-idx], dv = (tx&7)+8u
    u64 psum[4]  = {};
    const int nb  = (tx >> 3) << 5;
    const int dvb = tx & 7;

    for (int c = 0; c < 64; c++) {
        __syncthreads();
        *(float4*)&ks[lr][lc]   = kr0; *(float4*)&ks[lr][lc+4] = kr1;
        *(float4*)&vs[lr][lc]   = vr0; *(float4*)&vs[lr][lc+4] = vr1;
        if (c < 63) {
            const float* kp = kbase + (size_t)lr * HWN + ((c + 1) << 6) + lc;
            const float* vp = vbase + (size_t)lr * HWN + ((c + 1) << 6) + lc;
            kr0 = *(const float4*)kp; kr1 = *(const float4*)(kp + 4);
            vr0 = *(const float4*)vp; vr1 = *(const float4*)(vp + 4);
        }
        __syncthreads();

        // ---- S = q . k   (rows ty*8..+7 packed, cols tx*4..+3) ----
        u64 S2[4][4] = {};   // [col][rowpair]
        #pragma unroll 8
        for (int kk = 0; kk < DK; kk++) {
            float4 qa = *(const float4*)&qsT[kk][ty << 3];
            float4 qb = *(const float4*)&qsT[kk][(ty << 3) + 4];
            u64 q0 = pk(qa.x, qa.y), q1 = pk(qa.z, qa.w);
            u64 q2 = pk(qb.x, qb.y), q3 = pk(qb.z, qb.w);
            float4 k4 = *(const float4*)&ks[kk][tx << 2];
            u64 kp0 = pk(k4.x, k4.x), kp1 = pk(k4.y, k4.y);
            u64 kp2 = pk(k4.z, k4.z), kp3 = pk(k4.w, k4.w);
            S2[0][0]=fma2(q0,kp0,S2[0][0]); S2[0][1]=fma2(q1,kp0,S2[0][1]);
            S2[0][2]=fma2(q2,kp0,S2[0][2]); S2[0][3]=fma2(q3,kp0,S2[0][3]);
            S2[1][0]=fma2(q0,kp1,S2[1][0]); S2[1][1]=fma2(q1,kp1,S2[1][1]);
            S2[1][2]=fma2(q2,kp1,S2[1][2]); S2[1][3]=fma2(q3,kp1,S2[1][3]);
            S2[2][0]=fma2(q0,kp2,S2[2][0]); S2[2][1]=fma2(q1,kp2,S2[2][1]);
            S2[2][2]=fma2(q2,kp2,S2[2][2]); S2[2][3]=fma2(q3,kp2,S2[2][3]);
            S2[3][0]=fma2(q0,kp3,S2[3][0]); S2[3][1]=fma2(q1,kp3,S2[3][1]);
            S2[3][2]=fma2(q2,kp3,S2[3][2]); S2[3][3]=fma2(q3,kp3,S2[3][3]);
        }
        // ---- exp (base-2, scale folded) + store P transposed ----
        #pragma unroll
        for (int cc = 0; cc < 4; cc++) {
            #pragma unroll
            for (int i = 0; i < 4; i++) {
                float a, bb; upk(S2[cc][i], a, bb);
                u64 pp = pk(ex2(a), ex2(bb));
                psum[i] = add2(psum[i], pp);
                *(u64*)&psT[(tx << 2) + cc][(ty << 3) + (i << 1)] = pp;
            }
        }
        __syncthreads();

        // ---- O += P . V^T  (tx<8: n 0..31, tx>=8: n 32..63) ----
        #pragma unroll 8
        for (int s = 0; s < 32; s++) {
            const int n = nb + s;
            const float* pp = &psT[n][ty << 3];
            u64 p0 = *(const u64*)pp,       p1 = *(const u64*)(pp + 2);
            u64 p2 = *(const u64*)(pp + 4), p3 = *(const u64*)(pp + 6);
            float va = vs[dvb][n],      vb2 = vs[dvb + 8][n];
            float vc = vs[dvb + 16][n], vd  = vs[dvb + 24][n];
            u64 w0 = pk(va, va), w1 = pk(vb2, vb2), w2 = pk(vc, vc), w3 = pk(vd, vd);
            O2[0][0]=fma2(p0,w0,O2[0][0]); O2[1][0]=fma2(p1,w0,O2[1][0]);
            O2[2][0]=fma2(p2,w0,O2[2][0]); O2[3][0]=fma2(p3,w0,O2[3][0]);
            O2[0][1]=fma2(p0,w1,O2[0][1]); O2[1][1]=fma2(p1,w1,O2[1][1]);
            O2[2][1]=fma2(p2,w1,O2[2][1]); O2[3][1]=fma2(p3,w1,O2[3][1]);
            O2[0][2]=fma2(p0,w2,O2[0][2]); O2[1][2]=fma2(p1,w2,O2[1][2]);
            O2[2][2]=fma2(p2,w2,O2[2][2]); O2[3][2]=fma2(p3,w2,O2[3][2]);
            O2[0][3]=fma2(p0,w3,O2[0][3]); O2[1][3]=fma2(p1,w3,O2[1][3]);
            O2[2][3]=fma2(p2,w3,O2[2][3]); O2[3][3]=fma2(p3,w3,O2[3][3]);
        }
    }

    // reduce psum over tx (butterfly), O over tx-halves
    #pragma unroll
    for (int m = 1; m <= 8; m <<= 1)
        #pragma unroll
        for (int i = 0; i < 4; i++)
            psum[i] = add2(psum[i], __shfl_xor_sync(0xffffffffu, psum[i], m));
    #pragma unroll
    for (int i = 0; i < 4; i++)
        #pragma unroll
        for (int u = 0; u < 4; u++)
            O2[i][u] = add2(O2[i][u], __shfl_xor_sync(0xffffffffu, O2[i][u], 8));

    if (tx < 8) {
        #pragma unroll
        for (int i = 0; i < 4; i++) {
            float sa, sb; upk(psum[i], sa, sb);
            const float ia = 1.0f / sa, ib = 1.0f / sb;
            const int r = l0 + (ty << 3) + (i << 1);
            float* op = g_att + (size_t)(b * NL + r) * CKD + h * DV + dvb;
            #pragma unroll
            for (int u = 0; u < 4; u++) {
                float la, lb; upk(O2[i][u], la, lb);
                op[u * 8]       = la * ia;
                op[CKD + u * 8] = lb * ib;
            }
        }
    }
}

// ---------------------------------------------------------------------------
// proj + InstanceNorm over Nl + transpose (bw dropped — InstanceNorm-invariant)
// ---------------------------------------------------------------------------
__global__ __launch_bounds__(256) void proj_norm_kernel(
    const float* __restrict__ Ww, float* __restrict__ out)
{
    __shared__ float wsm[8][CKD];
    __shared__ float asmem[32][261];
    const int b  = blockIdx.y;
    const int o0 = blockIdx.x << 3;
    const int t  = threadIdx.x;
    const int rl = t & 31;
    const int ol = t >> 5;
    {
        int row = t >> 5;
        int c8  = (t & 31) << 3;
        *(float4*)&wsm[row][c8]     = *(const float4*)&Ww[(size_t)(o0 + row) * CKD + c8];
        *(float4*)&wsm[row][c8 + 4] = *(const float4*)&Ww[(size_t)(o0 + row) * CKD + c8 + 4];
    }
    float res[32];
    const int rr = t >> 3;
    const int cc = (t & 7) << 5;
    #pragma unroll
    for (int i = 0; i < 32; i++) {
        __syncthreads();
        const float* ap = g_att + (size_t)(b * NL + (i << 5) + rr) * CKD + cc;
        #pragma unroll
        for (int u = 0; u < 8; u++) {
            float4 v = *(const float4*)(ap + (u << 2));
            asmem[rr][cc + (u << 2) + 0] = v.x;
            asmem[rr][cc + (u << 2) + 1] = v.y;
            asmem[rr][cc + (u << 2) + 2] = v.z;
            asmem[rr][cc + (u << 2) + 3] = v.w;
        }
        __syncthreads();
        float acc = 0.f;
        #pragma unroll 8
        for (int c = 0; c < CKD; c++) acc += asmem[rl][c] * wsm[ol][c];
        res[i] = acc;
    }
    float s = 0.f, sq = 0.f;
    #pragma unroll
    for (int i = 0; i < 32; i++) { s += res[i]; sq += res[i] * res[i]; }
    #pragma unroll
    for (int off = 16; off; off >>= 1) {
        s  += __shfl_xor_sync(0xffffffffu, s,  off);
        sq += __shfl_xor_sync(0xffffffffu, sq, off);
    }
    const float mean = s * (1.0f / NL);
    const float var  = sq * (1.0f / NL) - mean * mean;
    const float rstd = rsqrtf(var + EPSI);
    const int o = o0 + ol;
    #pragma unroll
    for (int i = 0; i < 32; i++)
        out[(size_t)(b * NL + (i << 5) + rl) * CKD + o] = (res[i] - mean) * rstd;
}

// ---------------------------------------------------------------------------
extern "C" void kernel_launch(void* const* d_in, const int* in_sizes, int n_in,
                              void* d_out, int out_size)
{
    const float* l  = (const float*)d_in[0];
    const float* x  = (const float*)d_in[1];
    const float* Wq = (const float*)d_in[2];
    const float* bq = (const float*)d_in[3];
    const float* Wk = (const float*)d_in[4];
    const float* Wv = (const float*)d_in[6];
    const float* bv = (const float*)d_in[7];
    const float* Ww = (const float*)d_in[8];
    float* out = (float*)d_out;

    cudaFuncSetAttribute(attn_kernel,
                         cudaFuncAttributeMaxDynamicSharedMemorySize, ATTN_SMEM);

    gemm_q_kernel   <<<dim3(4, 64), 256>>>(l, Wq, bq);
    gemm_kv_kernel  <<<dim3(HWN / 128, 8, BATCH), 256>>>(x, Wk, Wv, bv);
    inorm_k_kernel  <<<BATCH * CKD, 256>>>();
    attn_kernel     <<<dim3(NL / 128, NH, BATCH), 256, ATTN_SMEM>>>();
    proj_norm_kernel<<<dim3(32, BATCH), 256>>>(Ww, out);
}

// round 5
// speedup vs baseline: 1.2470x; 1.2470x over previous
#include <cuda_runtime.h>

#define BATCH 4
#define NL    1024
#define HWN   4096
#define CIN   512
#define CKD   256
#define NH    8
#define DK    32
#define DV    32
#define MTOT  4096
#define EPSI  1e-5f
#define QSCALE 0.09016844f   /* (1/16) * log2(e) */
#define ATTN_SMEM 67584

typedef unsigned long long u64;

__device__ __forceinline__ u64 pk(float a, float b) {
    u64 r;
    asm("mov.b64 %0, {%1, %2};" : "=l"(r)
        : "r"(__float_as_uint(a)), "r"(__float_as_uint(b)));
    return r;
}
__device__ __forceinline__ void upk(u64 p, float& a, float& b) {
    unsigned x, y;
    asm("mov.b64 {%0, %1}, %2;" : "=r"(x), "=r"(y) : "l"(p));
    a = __uint_as_float(x); b = __uint_as_float(y);
}
__device__ __forceinline__ u64 fma2(u64 a, u64 b, u64 c) {
    u64 d;
    asm("fma.rn.f32x2 %0, %1, %2, %3;" : "=l"(d) : "l"(a), "l"(b), "l"(c));
    return d;
}
__device__ __forceinline__ u64 add2(u64 a, u64 b) {
    u64 d;
    asm("add.rn.f32x2 %0, %1, %2;" : "=l"(d) : "l"(a), "l"(b));
    return d;
}
__device__ __forceinline__ float ex2(float x) {
    float r; asm("ex2.approx.f32 %0, %1;" : "=f"(r) : "f"(x)); return r;
}

__device__ float g_qT[CKD * MTOT];                  // [ck][b*Nl]  4 MB
__device__ float g_k[(size_t)BATCH * CKD * HWN];    // [b, c, n]  16 MB
__device__ float g_v[(size_t)BATCH * CKD * HWN];    // [b, c, n]  16 MB
__device__ float g_att[BATCH * NL * CKD];           // [b*Nl, cv]  4 MB
__device__ float g_y[CKD * MTOT];                   // [o][b*Nl]   4 MB

// ---------------------------------------------------------------------------
// Generic f32x2 GEMM: out[c][m] = A[m][:KDIM] . W[c][:KDIM] (+ bias[c])
// tile 128 m x 64 c, out row stride MTOT.  (used for q and for projection)
// ---------------------------------------------------------------------------
template<int KDIM, bool BIAS>
__global__ __launch_bounds__(256) void gemm_T(
    const float* __restrict__ A, const float* __restrict__ W,
    const float* __restrict__ bias, float* __restrict__ out)
{
    __shared__ float As[16][132];
    __shared__ float Bs[16][68];
    const int m0 = blockIdx.x << 7;
    const int c0 = blockIdx.y << 6;
    const int t  = threadIdx.x;
    const int tx = t & 15, ty = t >> 4;
    const int ar = t >> 1, ak = (t & 1) << 3;
    const int bc = t >> 2, bk = (t & 3) << 2;
    u64 acc[4][4] = {};
    for (int k0 = 0; k0 < KDIM; k0 += 16) {
        float4 x0 = *(const float4*)&A[(size_t)(m0 + ar) * KDIM + k0 + ak];
        float4 x1 = *(const float4*)&A[(size_t)(m0 + ar) * KDIM + k0 + ak + 4];
        float4 wv = *(const float4*)&W[(size_t)(c0 + bc) * KDIM + k0 + bk];
        __syncthreads();
        As[ak+0][ar]=x0.x; As[ak+1][ar]=x0.y; As[ak+2][ar]=x0.z; As[ak+3][ar]=x0.w;
        As[ak+4][ar]=x1.x; As[ak+5][ar]=x1.y; As[ak+6][ar]=x1.z; As[ak+7][ar]=x1.w;
        Bs[bk+0][bc]=wv.x; Bs[bk+1][bc]=wv.y; Bs[bk+2][bc]=wv.z; Bs[bk+3][bc]=wv.w;
        __syncthreads();
        #pragma unroll
        for (int kk = 0; kk < 16; kk++) {
            float4 a0 = *(const float4*)&As[kk][tx << 2];
            float4 a1 = *(const float4*)&As[kk][64 + (tx << 2)];
            u64 np0 = pk(a0.x, a0.y), np1 = pk(a0.z, a0.w);
            u64 np2 = pk(a1.x, a1.y), np3 = pk(a1.z, a1.w);
            float4 cw = *(const float4*)&Bs[kk][ty << 2];
            u64 w0 = pk(cw.x, cw.x), w1 = pk(cw.y, cw.y);
            u64 w2 = pk(cw.z, cw.z), w3 = pk(cw.w, cw.w);
            acc[0][0]=fma2(np0,w0,acc[0][0]); acc[0][1]=fma2(np1,w0,acc[0][1]);
            acc[0][2]=fma2(np2,w0,acc[0][2]); acc[0][3]=fma2(np3,w0,acc[0][3]);
            acc[1][0]=fma2(np0,w1,acc[1][0]); acc[1][1]=fma2(np1,w1,acc[1][1]);
            acc[1][2]=fma2(np2,w1,acc[1][2]); acc[1][3]=fma2(np3,w1,acc[1][3]);
            acc[2][0]=fma2(np0,w2,acc[2][0]); acc[2][1]=fma2(np1,w2,acc[2][1]);
            acc[2][2]=fma2(np2,w2,acc[2][2]); acc[2][3]=fma2(np3,w2,acc[2][3]);
            acc[3][0]=fma2(np0,w3,acc[3][0]); acc[3][1]=fma2(np1,w3,acc[3][1]);
            acc[3][2]=fma2(np2,w3,acc[3][2]); acc[3][3]=fma2(np3,w3,acc[3][3]);
        }
    }
    #pragma unroll
    for (int i = 0; i < 4; i++) {
        const int cc = c0 + (ty << 2) + i;
        const float bb = BIAS ? bias[cc] : 0.f;
        float r0,r1,r2,r3,r4,r5,r6,r7;
        upk(acc[i][0], r0, r1); upk(acc[i][1], r2, r3);
        upk(acc[i][2], r4, r5); upk(acc[i][3], r6, r7);
        float* rp = out + (size_t)cc * MTOT + m0 + (tx << 2);
        *(float4*)rp        = make_float4(r0+bb, r1+bb, r2+bb, r3+bb);
        *(float4*)(rp + 64) = make_float4(r4+bb, r5+bb, r6+bb, r7+bb);
    }
}

// ---------------------------------------------------------------------------
// k/v GEMM, f32x2, tile 128n x 64c.  bk dropped (InstanceNorm-invariant).
// ---------------------------------------------------------------------------
__global__ __launch_bounds__(256) void gemm_kv_kernel(
    const float* __restrict__ X, const float* __restrict__ Wk,
    const float* __restrict__ Wv, const float* __restrict__ bv)
{
    __shared__ float As[16][132];
    __shared__ float Bs[16][68];
    const int b   = blockIdx.z;
    const int isv = blockIdx.y >> 2;
    const int c0  = (blockIdx.y & 3) << 6;
    const int n0  = blockIdx.x << 7;
    const float* W = isv ? Wv : Wk;
    const float* A = X + (size_t)b * HWN * CIN;
    const int t  = threadIdx.x;
    const int tx = t & 15, ty = t >> 4;
    const int ar = t >> 1, ak = (t & 1) << 3;
    const int bc = t >> 2, bk = (t & 3) << 2;
    u64 acc[4][4] = {};
    for (int k0 = 0; k0 < CIN; k0 += 16) {
        float4 x0 = *(const float4*)&A[(size_t)(n0 + ar) * CIN + k0 + ak];
        float4 x1 = *(const float4*)&A[(size_t)(n0 + ar) * CIN + k0 + ak + 4];
        float4 wv = *(const float4*)&W[(size_t)(c0 + bc) * CIN + k0 + bk];
        __syncthreads();
        As[ak+0][ar]=x0.x; As[ak+1][ar]=x0.y; As[ak+2][ar]=x0.z; As[ak+3][ar]=x0.w;
        As[ak+4][ar]=x1.x; As[ak+5][ar]=x1.y; As[ak+6][ar]=x1.z; As[ak+7][ar]=x1.w;
        Bs[bk+0][bc]=wv.x; Bs[bk+1][bc]=wv.y; Bs[bk+2][bc]=wv.z; Bs[bk+3][bc]=wv.w;
        __syncthreads();
        #pragma unroll
        for (int kk = 0; kk < 16; kk++) {
            float4 a0 = *(const float4*)&As[kk][tx << 2];
            float4 a1 = *(const float4*)&As[kk][64 + (tx << 2)];
            u64 np0 = pk(a0.x, a0.y), np1 = pk(a0.z, a0.w);
            u64 np2 = pk(a1.x, a1.y), np3 = pk(a1.z, a1.w);
            float4 cw = *(const float4*)&Bs[kk][ty << 2];
            u64 w0 = pk(cw.x, cw.x), w1 = pk(cw.y, cw.y);
            u64 w2 = pk(cw.z, cw.z), w3 = pk(cw.w, cw.w);
            acc[0][0]=fma2(np0,w0,acc[0][0]); acc[0][1]=fma2(np1,w0,acc[0][1]);
            acc[0][2]=fma2(np2,w0,acc[0][2]); acc[0][3]=fma2(np3,w0,acc[0][3]);
            acc[1][0]=fma2(np0,w1,acc[1][0]); acc[1][1]=fma2(np1,w1,acc[1][1]);
            acc[1][2]=fma2(np2,w1,acc[1][2]); acc[1][3]=fma2(np3,w1,acc[1][3]);
            acc[2][0]=fma2(np0,w2,acc[2][0]); acc[2][1]=fma2(np1,w2,acc[2][1]);
            acc[2][2]=fma2(np2,w2,acc[2][2]); acc[2][3]=fma2(np3,w2,acc[2][3]);
            acc[3][0]=fma2(np0,w3,acc[3][0]); acc[3][1]=fma2(np1,w3,acc[3][1]);
            acc[3][2]=fma2(np2,w3,acc[3][2]); acc[3][3]=fma2(np3,w3,acc[3][3]);
        }
    }
    float* basep = (isv ? g_v : g_k) + (size_t)b * CKD * HWN;
    #pragma unroll
    for (int i = 0; i < 4; i++) {
        const int cc = c0 + (ty << 2) + i;
        const float bias = isv ? bv[cc] : 0.f;
        float r0,r1,r2,r3,r4,r5,r6,r7;
        upk(acc[i][0], r0, r1); upk(acc[i][1], r2, r3);
        upk(acc[i][2], r4, r5); upk(acc[i][3], r6, r7);
        float* rp = basep + (size_t)cc * HWN + n0 + (tx << 2);
        *(float4*)rp        = make_float4(r0+bias, r1+bias, r2+bias, r3+bias);
        *(float4*)(rp + 64) = make_float4(r4+bias, r5+bias, r6+bias, r7+bias);
    }
}

// ---------------------------------------------------------------------------
// InstanceNorm over HW on g_k
// ---------------------------------------------------------------------------
__global__ __launch_bounds__(256) void inorm_k_kernel()
{
    __shared__ float red[16];
    const int row = blockIdx.x;
    float4* p4 = reinterpret_cast<float4*>(g_k + (size_t)row * HWN);
    const int t = threadIdx.x;
    float4 v[4];
    float s = 0.f, sq = 0.f;
    #pragma unroll
    for (int i = 0; i < 4; i++) {
        v[i] = p4[t + 256 * i];
        s  += v[i].x + v[i].y + v[i].z + v[i].w;
        sq += v[i].x * v[i].x + v[i].y * v[i].y + v[i].z * v[i].z + v[i].w * v[i].w;
    }
    #pragma unroll
    for (int off = 16; off; off >>= 1) {
        s  += __shfl_xor_sync(0xffffffffu, s,  off);
        sq += __shfl_xor_sync(0xffffffffu, sq, off);
    }
    if ((t & 31) == 0) { red[t >> 5] = s; red[8 + (t >> 5)] = sq; }
    __syncthreads();
    if (t == 0) {
        float S = 0.f, Q = 0.f;
        #pragma unroll
        for (int i = 0; i < 8; i++) { S += red[i]; Q += red[8 + i]; }
        float mean = S * (1.f / HWN);
        float var  = Q * (1.f / HWN) - mean * mean;
        red[0] = mean;
        red[1] = rsqrtf(var + EPSI);
    }
    __syncthreads();
    const float mean = red[0], rstd = red[1];
    #pragma unroll
    for (int i = 0; i < 4; i++) {
        v[i].x = (v[i].x - mean) * rstd;
        v[i].y = (v[i].y - mean) * rstd;
        v[i].z = (v[i].z - mean) * rstd;
        v[i].w = (v[i].w - mean) * rstd;
        p4[t + 256 * i] = v[i];
    }
}

// ---------------------------------------------------------------------------
// Attention, f32x2, bank-tuned smem.  128 q-rows/block, 64-n chunks.
// ---------------------------------------------------------------------------
__global__ void __launch_bounds__(256, 2) attn_kernel()
{
    extern __shared__ float sm[];
    float (*qsT)[132] = (float(*)[132])sm;            // [d][row]
    float (*ks)[68]   = (float(*)[68])(sm + 4224);    // [d][n]
    float (*vs)[68]   = (float(*)[68])(sm + 6400);    // [dv][n]
    float (*psT)[130] = (float(*)[130])(sm + 8576);   // [n][row]  stride 130!

    const int b = blockIdx.z, h = blockIdx.y, l0 = blockIdx.x << 7;
    const int t = threadIdx.x, tx = t & 15, ty = t >> 4;

    {   // stage Q from g_qT (coalesced along rows), pre-scaled
        const int d = t >> 3, rb = (t & 7) << 4;
        const float* qp = g_qT + (size_t)(h * DK + d) * MTOT + b * NL + l0 + rb;
        #pragma unroll
        for (int j = 0; j < 4; j++) {
            float4 v = *(const float4*)(qp + 4 * j);
            qsT[d][rb + 4*j + 0] = v.x * QSCALE;
            qsT[d][rb + 4*j + 1] = v.y * QSCALE;
            qsT[d][rb + 4*j + 2] = v.z * QSCALE;
            qsT[d][rb + 4*j + 3] = v.w * QSCALE;
        }
    }

    const float* kbase = g_k + ((size_t)b * CKD + h * DK) * HWN;
    const float* vbase = g_v + ((size_t)b * CKD + h * DV) * HWN;
    const int lr = t >> 3, lc = (t & 7) << 3;

    float4 kr0 = *(const float4*)(kbase + (size_t)lr * HWN + lc);
    float4 kr1 = *(const float4*)(kbase + (size_t)lr * HWN + lc + 4);
    float4 vr0 = *(const float4*)(vbase + (size_t)lr * HWN + lc);
    float4 vr1 = *(const float4*)(vbase + (size_t)lr * HWN + lc + 4);

    u64 O2[4][4] = {};          // [rowpair][dv-idx], dv = (tx&7)+8u
    u64 psum[4]  = {};
    const int half = tx >> 3;   // PV n-parity
    const int dvb  = tx & 7;
    const int rb8  = ty << 3;

    for (int c = 0; c < 64; c++) {
        __syncthreads();
        *(float4*)&ks[lr][lc]   = kr0; *(float4*)&ks[lr][lc+4] = kr1;
        *(float4*)&vs[lr][lc]   = vr0; *(float4*)&vs[lr][lc+4] = vr1;
        if (c < 63) {
            const float* kp = kbase + (size_t)lr * HWN + ((c + 1) << 6) + lc;
            const float* vp = vbase + (size_t)lr * HWN + ((c + 1) << 6) + lc;
            kr0 = *(const float4*)kp; kr1 = *(const float4*)(kp + 4);
            vr0 = *(const float4*)vp; vr1 = *(const float4*)(vp + 4);
        }
        __syncthreads();

        // ---- S = q.k : cols n = {2tx, 2tx+1, 2tx+32, 2tx+33} ----
        u64 S2[4][4] = {};   // [cc][rowpair]
        #pragma unroll 8
        for (int kk = 0; kk < DK; kk++) {
            u64 q0 = *(const u64*)&qsT[kk][rb8];
            u64 q1 = *(const u64*)&qsT[kk][rb8 + 2];
            u64 q2 = *(const u64*)&qsT[kk][rb8 + 4];
            u64 q3 = *(const u64*)&qsT[kk][rb8 + 6];
            float2 kA = *(const float2*)&ks[kk][tx << 1];
            float2 kB = *(const float2*)&ks[kk][(tx << 1) + 32];
            u64 kp0 = pk(kA.x, kA.x), kp1 = pk(kA.y, kA.y);
            u64 kp2 = pk(kB.x, kB.x), kp3 = pk(kB.y, kB.y);
            S2[0][0]=fma2(q0,kp0,S2[0][0]); S2[0][1]=fma2(q1,kp0,S2[0][1]);
            S2[0][2]=fma2(q2,kp0,S2[0][2]); S2[0][3]=fma2(q3,kp0,S2[0][3]);
            S2[1][0]=fma2(q0,kp1,S2[1][0]); S2[1][1]=fma2(q1,kp1,S2[1][1]);
            S2[1][2]=fma2(q2,kp1,S2[1][2]); S2[1][3]=fma2(q3,kp1,S2[1][3]);
            S2[2][0]=fma2(q0,kp2,S2[2][0]); S2[2][1]=fma2(q1,kp2,S2[2][1]);
            S2[2][2]=fma2(q2,kp2,S2[2][2]); S2[2][3]=fma2(q3,kp2,S2[2][3]);
            S2[3][0]=fma2(q0,kp3,S2[3][0]); S2[3][1]=fma2(q1,kp3,S2[3][1]);
            S2[3][2]=fma2(q2,kp3,S2[3][2]); S2[3][3]=fma2(q3,kp3,S2[3][3]);
        }
        // ---- exp + transposed store (stride 130 -> 2-way max) ----
        const int nc0 = tx << 1;
        #pragma unroll
        for (int cc = 0; cc < 4; cc++) {
            const int nn = nc0 + (cc & 1) + ((cc >> 1) << 5);
            #pragma unroll
            for (int i = 0; i < 4; i++) {
                float a, bb; upk(S2[cc][i], a, bb);
                u64 pp = pk(ex2(a), ex2(bb));
                psum[i] = add2(psum[i], pp);
                *(u64*)&psT[nn][rb8 + (i << 1)] = pp;
            }
        }
        __syncthreads();

        // ---- O += P.V^T : n = 2s + half (parity-interleaved) ----
        #pragma unroll 8
        for (int s = 0; s < 32; s++) {
            const int n = (s << 1) | half;
            const float* pp = &psT[n][rb8];
            u64 p0 = *(const u64*)pp,       p1 = *(const u64*)(pp + 2);
            u64 p2 = *(const u64*)(pp + 4), p3 = *(const u64*)(pp + 6);
            float va = vs[dvb][n],      vb2 = vs[dvb + 8][n];
            float vc = vs[dvb + 16][n], vd  = vs[dvb + 24][n];
            u64 w0 = pk(va, va), w1 = pk(vb2, vb2), w2 = pk(vc, vc), w3 = pk(vd, vd);
            O2[0][0]=fma2(p0,w0,O2[0][0]); O2[1][0]=fma2(p1,w0,O2[1][0]);
            O2[2][0]=fma2(p2,w0,O2[2][0]); O2[3][0]=fma2(p3,w0,O2[3][0]);
            O2[0][1]=fma2(p0,w1,O2[0][1]); O2[1][1]=fma2(p1,w1,O2[1][1]);
            O2[2][1]=fma2(p2,w1,O2[2][1]); O2[3][1]=fma2(p3,w1,O2[3][1]);
            O2[0][2]=fma2(p0,w2,O2[0][2]); O2[1][2]=fma2(p1,w2,O2[1][2]);
            O2[2][2]=fma2(p2,w2,O2[2][2]); O2[3][2]=fma2(p3,w2,O2[3][2]);
            O2[0][3]=fma2(p0,w3,O2[0][3]); O2[1][3]=fma2(p1,w3,O2[1][3]);
            O2[2][3]=fma2(p2,w3,O2[2][3]); O2[3][3]=fma2(p3,w3,O2[3][3]);
        }
    }

    #pragma unroll
    for (int m = 1; m <= 8; m <<= 1)
        #pragma unroll
        for (int i = 0; i < 4; i++)
            psum[i] = add2(psum[i], __shfl_xor_sync(0xffffffffu, psum[i], m));
    #pragma unroll
    for (int i = 0; i < 4; i++)
        #pragma unroll
        for (int u = 0; u < 4; u++)
            O2[i][u] = add2(O2[i][u], __shfl_xor_sync(0xffffffffu, O2[i][u], 8));

    if (tx < 8) {
        #pragma unroll
        for (int i = 0; i < 4; i++) {
            float sa, sb; upk(psum[i], sa, sb);
            const float ia = 1.0f / sa, ib = 1.0f / sb;
            const int r = l0 + rb8 + (i << 1);
            float* op = g_att + (size_t)(b * NL + r) * CKD + h * DV + dvb;
            #pragma unroll
            for (int u = 0; u < 4; u++) {
                float la, lb; upk(O2[i][u], la, lb);
                op[u * 8]       = la * ia;
                op[CKD + u * 8] = lb * ib;
            }
        }
    }
}

// ---------------------------------------------------------------------------
// InstanceNorm over Nl on g_y[o][b*Nl+l] + transposed write out[b,l,o]
// grid (CKD/32, BATCH), 256 threads
// ---------------------------------------------------------------------------
__global__ __launch_bounds__(256) void norm_t_kernel(float* __restrict__ out)
{
    __shared__ float tile[32][33];
    __shared__ float meanv[32], rstdv[32];
    const int b = blockIdx.y, o0 = blockIdx.x << 5;
    const int t = threadIdx.x, lane = t & 31, w = t >> 5;

    #pragma unroll
    for (int j = 0; j < 4; j++) {
        const int ol = (w << 2) + j;
        const float* yp = g_y + (size_t)(o0 + ol) * MTOT + b * NL;
        float s = 0.f, sq = 0.f;
        #pragma unroll
        for (int i = 0; i < 8; i++) {
            float4 v = *(const float4*)&yp[(i * 32 + lane) * 4];
            s  += v.x + v.y + v.z + v.w;
            sq += v.x*v.x + v.y*v.y + v.z*v.z + v.w*v.w;
        }
        #pragma unroll
        for (int off = 16; off; off >>= 1) {
            s  += __shfl_xor_sync(0xffffffffu, s,  off);
            sq += __shfl_xor_sync(0xffffffffu, sq, off);
        }
        if (lane == 0) {
            float mean = s * (1.f / NL);
            float var  = sq * (1.f / NL) - mean * mean;
            meanv[ol] = mean;
            rstdv[ol] = rsqrtf(var + EPSI);
        }
    }
    __syncthreads();
    const float mo = meanv[lane], ro = rstdv[lane];
    for (int l0 = 0; l0 < NL; l0 += 32) {
        __syncthreads();
        #pragma unroll
        for (int j = 0; j < 4; j++)
            tile[w + 8*j][lane] =
                g_y[(size_t)(o0 + w + 8*j) * MTOT + b * NL + l0 + lane];
        __syncthreads();
        #pragma unroll
        for (int j = 0; j < 4; j++)
            out[(size_t)(b * NL + l0 + w + 8*j) * CKD + o0 + lane] =
                (tile[lane][w + 8*j] - mo) * ro;
    }
}

// ---------------------------------------------------------------------------
extern "C" void kernel_launch(void* const* d_in, const int* in_sizes, int n_in,
                              void* d_out, int out_size)
{
    const float* l  = (const float*)d_in[0];
    const float* x  = (const float*)d_in[1];
    const float* Wq = (const float*)d_in[2];
    const float* bq = (const float*)d_in[3];
    const float* Wk = (const float*)d_in[4];
    const float* Wv = (const float*)d_in[6];
    const float* bv = (const float*)d_in[7];
    const float* Ww = (const float*)d_in[8];
    float* out = (float*)d_out;

    float* qT; cudaGetSymbolAddress((void**)&qT, g_qT);
    float* att; cudaGetSymbolAddress((void**)&att, g_att);
    float* yy; cudaGetSymbolAddress((void**)&yy, g_y);

    cudaFuncSetAttribute(attn_kernel,
                         cudaFuncAttributeMaxDynamicSharedMemorySize, ATTN_SMEM);

    gemm_T<CIN, true>  <<<dim3(32, 4), 256>>>(l, Wq, bq, qT);
    gemm_kv_kernel     <<<dim3(HWN / 128, 8, BATCH), 256>>>(x, Wk, Wv, bv);
    inorm_k_kernel     <<<BATCH * CKD, 256>>>();
    attn_kernel        <<<dim3(NL / 128, NH, BATCH), 256, ATTN_SMEM>>>();
    gemm_T<CKD, false> <<<dim3(32, 4), 256>>>(att, Ww, nullptr, yy);
    norm_t_kernel      <<<dim3(CKD / 32, BATCH), 256>>>(out);
}

// round 7
// speedup vs baseline: 2.1886x; 1.7551x over previous
#include <cuda_runtime.h>
#include <cuda_fp16.h>
#include <cstdint>

#define BATCH 4
#define NL    1024
#define HWN   4096
#define CIN   512
#define CKD   256
#define NH    8
#define DK    32
#define DV    32
#define MTOT  4096
#define EPSI  1e-5f
#define QSCALE 0.09016844f   /* (1/16) * log2(e) */

typedef unsigned long long u64;

// ---------------- fp32x2 helpers ----------------
__device__ __forceinline__ u64 pk(float a, float b) {
    u64 r;
    asm("mov.b64 %0, {%1, %2};" : "=l"(r)
        : "r"(__float_as_uint(a)), "r"(__float_as_uint(b)));
    return r;
}
__device__ __forceinline__ void upk(u64 p, float& a, float& b) {
    unsigned x, y;
    asm("mov.b64 {%0, %1}, %2;" : "=r"(x), "=r"(y) : "l"(p));
    a = __uint_as_float(x); b = __uint_as_float(y);
}
__device__ __forceinline__ u64 fma2(u64 a, u64 b, u64 c) {
    u64 d;
    asm("fma.rn.f32x2 %0, %1, %2, %3;" : "=l"(d) : "l"(a), "l"(b), "l"(c));
    return d;
}
__device__ __forceinline__ float ex2(float x) {
    float r; asm("ex2.approx.f32 %0, %1;" : "=f"(r) : "f"(x)); return r;
}
__device__ __forceinline__ uint32_t h2pack(float lo, float hi) {
    __half2 h = __floats2half2_rn(lo, hi);     // .x = lo half
    return *(uint32_t*)&h;
}
__device__ __forceinline__ uint32_t smem_u32(const void* p) {
    uint32_t a;
    asm("{ .reg .u64 t; cvta.to.shared.u64 t, %1; cvt.u32.u64 %0, t; }"
        : "=r"(a) : "l"(p));
    return a;
}
__device__ __forceinline__ void ldsm4(uint32_t* r, uint32_t addr) {
    asm volatile("ldmatrix.sync.aligned.m8n8.x4.shared.b16 {%0,%1,%2,%3}, [%4];"
        : "=r"(r[0]), "=r"(r[1]), "=r"(r[2]), "=r"(r[3]) : "r"(addr));
}
__device__ __forceinline__ void mma16816(float* c, const uint32_t* a,
                                         const uint32_t b0, const uint32_t b1) {
    asm volatile(
        "mma.sync.aligned.m16n8k16.row.col.f32.f16.f16.f32 "
        "{%0,%1,%2,%3},{%4,%5,%6,%7},{%8,%9},{%0,%1,%2,%3};"
        : "+f"(c[0]), "+f"(c[1]), "+f"(c[2]), "+f"(c[3])
        : "r"(a[0]), "r"(a[1]), "r"(a[2]), "r"(a[3]), "r"(b0), "r"(b1));
}

// ---------------- scratch ----------------
__device__ __half g_qh[MTOT * CKD];                       // [m][ck] hi, prescaled
__device__ __half g_ql[MTOT * CKD];                       // [m][ck] lo
__device__ float  g_k [(size_t)BATCH * CKD * HWN];        // fp32 [b,c,n]
__device__ __half g_kh[(size_t)BATCH * NH * HWN * DK];    // [b,h][n][dk]
__device__ __half g_vh[(size_t)BATCH * CKD * HWN];        // [b,c,n]
__device__ float  g_att[BATCH * NL * CKD];
__device__ float  g_y[CKD * MTOT];

// ---------------------------------------------------------------------------
// q = (l @ Wq^T + bq) * QSCALE -> fp16 hi/lo
// ---------------------------------------------------------------------------
__global__ __launch_bounds__(256) void gemm_q_kernel(
    const float* __restrict__ L, const float* __restrict__ Wq,
    const float* __restrict__ bq)
{
    __shared__ float As[16][64];
    __shared__ float Bs[16][64];
    const int m0 = blockIdx.y << 6;
    const int c0 = blockIdx.x << 6;
    const int t  = threadIdx.x;
    const int tx = t & 15, ty = t >> 4;
    const int li = t >> 2;
    const int lk = (t & 3) << 2;
    float acc[4][4] = {};
    for (int k0 = 0; k0 < CIN; k0 += 16) {
        float4 a = *(const float4*)&L [(size_t)(m0 + li) * CIN + k0 + lk];
        float4 w = *(const float4*)&Wq[(size_t)(c0 + li) * CIN + k0 + lk];
        __syncthreads();
        As[lk+0][li] = a.x; As[lk+1][li] = a.y; As[lk+2][li] = a.z; As[lk+3][li] = a.w;
        Bs[lk+0][li] = w.x; Bs[lk+1][li] = w.y; Bs[lk+2][li] = w.z; Bs[lk+3][li] = w.w;
        __syncthreads();
        #pragma unroll
        for (int kk = 0; kk < 16; kk++) {
            float4 av = *(const float4*)&As[kk][ty << 2];
            float4 bv = *(const float4*)&Bs[kk][tx << 2];
            float ar[4] = {av.x, av.y, av.z, av.w};
            float br[4] = {bv.x, bv.y, bv.z, bv.w};
            #pragma unroll
            for (int i = 0; i < 4; i++)
                #pragma unroll
                for (int j = 0; j < 4; j++) acc[i][j] += ar[i] * br[j];
        }
    }
    #pragma unroll
    for (int i = 0; i < 4; i++) {
        #pragma unroll
        for (int j = 0; j < 4; j++) {
            float f = (acc[i][j] + bq[c0 + (tx << 2) + j]) * QSCALE;
            __half hi = __float2half_rn(f);
            __half lo = __float2half_rn(f - __half2float(hi));
            size_t idx = (size_t)(m0 + (ty << 2) + i) * CKD + c0 + (tx << 2) + j;
            g_qh[idx] = hi;
            g_ql[idx] = lo;
        }
    }
}

// ---------------------------------------------------------------------------
// k/v GEMM f32x2. K -> fp32 g_k (bk dropped), V -> fp16 g_vh.
// ---------------------------------------------------------------------------
__global__ __launch_bounds__(256) void gemm_kv_kernel(
    const float* __restrict__ X, const float* __restrict__ Wk,
    const float* __restrict__ Wv, const float* __restrict__ bv)
{
    __shared__ float As[16][132];
    __shared__ float Bs[16][68];
    const int b   = blockIdx.z;
    const int isv = blockIdx.y >> 2;
    const int c0  = (blockIdx.y & 3) << 6;
    const int n0  = blockIdx.x << 7;
    const float* W = isv ? Wv : Wk;
    const float* A = X + (size_t)b * HWN * CIN;
    const int t  = threadIdx.x;
    const int tx = t & 15, ty = t >> 4;
    const int ar = t >> 1, ak = (t & 1) << 3;
    const int bc = t >> 2, bk = (t & 3) << 2;
    u64 acc[4][4] = {};
    for (int k0 = 0; k0 < CIN; k0 += 16) {
        float4 x0 = *(const float4*)&A[(size_t)(n0 + ar) * CIN + k0 + ak];
        float4 x1 = *(const float4*)&A[(size_t)(n0 + ar) * CIN + k0 + ak + 4];
        float4 wv = *(const float4*)&W[(size_t)(c0 + bc) * CIN + k0 + bk];
        __syncthreads();
        As[ak+0][ar]=x0.x; As[ak+1][ar]=x0.y; As[ak+2][ar]=x0.z; As[ak+3][ar]=x0.w;
        As[ak+4][ar]=x1.x; As[ak+5][ar]=x1.y; As[ak+6][ar]=x1.z; As[ak+7][ar]=x1.w;
        Bs[bk+0][bc]=wv.x; Bs[bk+1][bc]=wv.y; Bs[bk+2][bc]=wv.z; Bs[bk+3][bc]=wv.w;
        __syncthreads();
        #pragma unroll
        for (int kk = 0; kk < 16; kk++) {
            float4 a0 = *(const float4*)&As[kk][tx << 2];
            float4 a1 = *(const float4*)&As[kk][64 + (tx << 2)];
            u64 np0 = pk(a0.x, a0.y), np1 = pk(a0.z, a0.w);
            u64 np2 = pk(a1.x, a1.y), np3 = pk(a1.z, a1.w);
            float4 cw = *(const float4*)&Bs[kk][ty << 2];
            u64 w0 = pk(cw.x, cw.x), w1 = pk(cw.y, cw.y);
            u64 w2 = pk(cw.z, cw.z), w3 = pk(cw.w, cw.w);
            acc[0][0]=fma2(np0,w0,acc[0][0]); acc[0][1]=fma2(np1,w0,acc[0][1]);
            acc[0][2]=fma2(np2,w0,acc[0][2]); acc[0][3]=fma2(np3,w0,acc[0][3]);
            acc[1][0]=fma2(np0,w1,acc[1][0]); acc[1][1]=fma2(np1,w1,acc[1][1]);
            acc[1][2]=fma2(np2,w1,acc[1][2]); acc[1][3]=fma2(np3,w1,acc[1][3]);
            acc[2][0]=fma2(np0,w2,acc[2][0]); acc[2][1]=fma2(np1,w2,acc[2][1]);
            acc[2][2]=fma2(np2,w2,acc[2][2]); acc[2][3]=fma2(np3,w2,acc[2][3]);
            acc[3][0]=fma2(np0,w3,acc[3][0]); acc[3][1]=fma2(np1,w3,acc[3][1]);
            acc[3][2]=fma2(np2,w3,acc[3][2]); acc[3][3]=fma2(np3,w3,acc[3][3]);
        }
    }
    #pragma unroll
    for (int i = 0; i < 4; i++) {
        const int cc = c0 + (ty << 2) + i;
        float r0,r1,r2,r3,r4,r5,r6,r7;
        upk(acc[i][0], r0, r1); upk(acc[i][1], r2, r3);
        upk(acc[i][2], r4, r5); upk(acc[i][3], r6, r7);
        if (!isv) {
            float* rp = g_k + ((size_t)b * CKD + cc) * HWN + n0 + (tx << 2);
            *(float4*)rp        = make_float4(r0, r1, r2, r3);
            *(float4*)(rp + 64) = make_float4(r4, r5, r6, r7);
        } else {
            const float bias = bv[cc];
            __half* vp = g_vh + ((size_t)b * CKD + cc) * HWN + n0 + (tx << 2);
            *(uint2*)vp        = make_uint2(h2pack(r0+bias, r1+bias), h2pack(r2+bias, r3+bias));
            *(uint2*)(vp + 64) = make_uint2(h2pack(r4+bias, r5+bias), h2pack(r6+bias, r7+bias));
        }
    }
}

// ---------------------------------------------------------------------------
// InstanceNorm over HW on g_k (fp32, in place)
// ---------------------------------------------------------------------------
__global__ __launch_bounds__(256) void inorm_k_kernel()
{
    __shared__ float red[16];
    const int row = blockIdx.x;
    float4* p4 = reinterpret_cast<float4*>(g_k + (size_t)row * HWN);
    const int t = threadIdx.x;
    float4 v[4];
    float s = 0.f, sq = 0.f;
    #pragma unroll
    for (int i = 0; i < 4; i++) {
        v[i] = p4[t + 256 * i];
        s  += v[i].x + v[i].y + v[i].z + v[i].w;
        sq += v[i].x * v[i].x + v[i].y * v[i].y + v[i].z * v[i].z + v[i].w * v[i].w;
    }
    #pragma unroll
    for (int off = 16; off; off >>= 1) {
        s  += __shfl_xor_sync(0xffffffffu, s,  off);
        sq += __shfl_xor_sync(0xffffffffu, sq, off);
    }
    if ((t & 31) == 0) { red[t >> 5] = s; red[8 + (t >> 5)] = sq; }
    __syncthreads();
    if (t == 0) {
        float S = 0.f, Q = 0.f;
        #pragma unroll
        for (int i = 0; i < 8; i++) { S += red[i]; Q += red[8 + i]; }
        float mean = S * (1.f / HWN);
        float var  = Q * (1.f / HWN) - mean * mean;
        red[0] = mean;
        red[1] = rsqrtf(var + EPSI);
    }
    __syncthreads();
    const float mean = red[0], rstd = red[1];
    #pragma unroll
    for (int i = 0; i < 4; i++) {
        v[i].x = (v[i].x - mean) * rstd;
        v[i].y = (v[i].y - mean) * rstd;
        v[i].z = (v[i].z - mean) * rstd;
        v[i].w = (v[i].w - mean) * rstd;
        p4[t + 256 * i] = v[i];
    }
}

// ---------------------------------------------------------------------------
// Transpose normalized K -> g_kh [b,h][n][dk] fp16
// ---------------------------------------------------------------------------
__global__ __launch_bounds__(256) void convert_k_kernel()
{
    __shared__ float tile[32][132];
    const int b = blockIdx.z, h = blockIdx.y, n0 = blockIdx.x << 7;
    const int t = threadIdx.x;
    {
        const int dk = t >> 3, seg = (t & 7) << 4;
        const float* src = g_k + ((size_t)b * CKD + h * DK + dk) * HWN + n0 + seg;
        #pragma unroll
        for (int u = 0; u < 4; u++) {
            float4 v = *(const float4*)(src + 4 * u);
            tile[dk][seg + 4*u + 0] = v.x;
            tile[dk][seg + 4*u + 1] = v.y;
            tile[dk][seg + 4*u + 2] = v.z;
            tile[dk][seg + 4*u + 3] = v.w;
        }
    }
    __syncthreads();
    const int n = t >> 1, part = t & 1;
    uint32_t w[8];
    #pragma unroll
    for (int j = 0; j < 8; j++)
        w[j] = h2pack(tile[part*16 + 2*j][n], tile[part*16 + 2*j + 1][n]);
    __half* dst = g_kh + ((size_t)(b * NH + h) * HWN + n0 + n) * DK + part * 16;
    ((uint4*)dst)[0] = make_uint4(w[0], w[1], w[2], w[3]);
    ((uint4*)dst)[1] = make_uint4(w[4], w[5], w[6], w[7]);
}

// ---------------------------------------------------------------------------
// HMMA attention: grid (NL/128, NH, BATCH), 256 threads (8 warps, 16 rows each)
// Q: fp16 hi/lo (2 QK terms); K,V,P: fp16 single.  fp32 accum, ex2 softmax.
// ---------------------------------------------------------------------------
__global__ __launch_bounds__(256) void attn_hmma_kernel()
{
    __shared__ __align__(16) __half qs_h[128 * 32];   // swizzled [row][dk]
    __shared__ __align__(16) __half qs_l[128 * 32];
    __shared__ __align__(16) __half ks[64 * 32];      // [key][dk]
    __shared__ __align__(16) __half vsm[32 * 64];     // [dv][key]

    const int b = blockIdx.z, h = blockIdx.y, l0 = blockIdx.x << 7;
    const int t = threadIdx.x, w = t >> 5, lane = t & 31;
    const int g = lane >> 2, l = lane & 3;

    {   // stage Q (hi+lo), swizzle chunk ^= (row>>1)&3
        const int row = t >> 1, cp = (t & 1) << 1;
        const uint4* srch = (const uint4*)(g_qh + (size_t)(b * NL + l0 + row) * CKD + h * DK);
        const uint4* srcl = (const uint4*)(g_ql + (size_t)(b * NL + l0 + row) * CKD + h * DK);
        const int sw = (row >> 1) & 3;
        ((uint4*)qs_h)[row * 4 + (cp ^ sw)]       = srch[cp];
        ((uint4*)qs_h)[row * 4 + ((cp + 1) ^ sw)] = srch[cp + 1];
        ((uint4*)qs_l)[row * 4 + (cp ^ sw)]       = srcl[cp];
        ((uint4*)qs_l)[row * 4 + ((cp + 1) ^ sw)] = srcl[cp + 1];
    }
    __syncthreads();

    uint32_t Ah[2][4], Al[2][4];
    {   // Q fragments: x4 ldmatrix per kstep per (hi,lo)
        const int row = (w << 4) + (lane & 7) + ((lane >> 3) & 1) * 8;
        const int kc  = lane >> 4;                 // 0/1
        const int sw  = (row >> 1) & 3;
        #pragma unroll
        for (int s = 0; s < 2; s++) {
            const uint32_t off = (row * 4 + (((s << 1) + kc) ^ sw)) * 16;
            ldsm4(Ah[s], smem_u32(qs_h) + off);
            ldsm4(Al[s], smem_u32(qs_l) + off);
        }
    }

    const __half* kg = g_kh + (size_t)(b * NH + h) * HWN * DK;
    const __half* vg = g_vh + ((size_t)b * CKD + h * DV) * HWN;
    const uint32_t ksb = smem_u32(ks), vsb = smem_u32(vsm);

    const int krow = t >> 2, kck = t & 3;          // K: 64 rows x 4 x 16B
    const int vrow = t >> 3, vck = t & 7;          // V: 32 rows x 8 x 16B
    const uint4* kg4 = (const uint4*)kg;
    const uint4* vg4 = (const uint4*)vg;
    uint4 krv = kg4[krow * 4 + kck];
    uint4 vrv = vg4[(size_t)vrow * (HWN / 8) + vck];

    float O[4][4] = {};
    float ps0 = 0.f, ps1 = 0.f;

    for (int c = 0; c < 64; c++) {
        __syncthreads();
        ((uint4*)ks)[krow * 4 + (kck ^ ((krow >> 1) & 3))] = krv;
        ((uint4*)vsm)[vrow * 8 + (vck ^ (vrow & 7))]       = vrv;
        if (c < 63) {
            krv = kg4[((c + 1) * 64 + krow) * 4 + kck];
            vrv = vg4[(size_t)vrow * (HWN / 8) + (c + 1) * 8 + vck];
        }
        __syncthreads();

        // ---- S = Q.K^T : 8 n-tiles of 8 keys ----
        float S[8][4];
        #pragma unroll
        for (int j = 0; j < 8; j++) { S[j][0]=0.f; S[j][1]=0.f; S[j][2]=0.f; S[j][3]=0.f; }
        #pragma unroll
        for (int j = 0; j < 8; j++) {
            const int row = (j << 3) + (lane & 7);
            uint32_t bk_[4];
            ldsm4(bk_, ksb + (row * 4 + ((lane >> 3) ^ ((row >> 1) & 3))) * 16);
            mma16816(S[j], Ah[0], bk_[0], bk_[1]);
            mma16816(S[j], Ah[1], bk_[2], bk_[3]);
            mma16816(S[j], Al[0], bk_[0], bk_[1]);
            mma16816(S[j], Al[1], bk_[2], bk_[3]);
        }

        // ---- exp + psum + pack P fragments ----
        uint32_t Ph[4][4];
        #pragma unroll
        for (int j = 0; j < 8; j++) {
            float p0 = ex2(S[j][0]), p1 = ex2(S[j][1]);
            float p2 = ex2(S[j][2]), p3 = ex2(S[j][3]);
            ps0 += p0 + p1;
            ps1 += p2 + p3;
            Ph[j >> 1][(j & 1) * 2 + 0] = h2pack(p0, p1);
            Ph[j >> 1][(j & 1) * 2 + 1] = h2pack(p2, p3);
        }

        // ---- O += P.V^T : 4 dv-tiles x 4 ksteps ----
        #pragma unroll
        for (int j = 0; j < 4; j++) {
            #pragma unroll
            for (int s2 = 0; s2 < 2; s2++) {
                const int row = (j << 3) + (lane & 7);
                uint32_t bv_[4];
                ldsm4(bv_, vsb + (row * 8 + (((s2 << 2) + (lane >> 3)) ^ (row & 7))) * 16);
                mma16816(O[j], Ph[2 * s2],     bv_[0], bv_[1]);
                mma16816(O[j], Ph[2 * s2 + 1], bv_[2], bv_[3]);
            }
        }
    }

    // reduce psum across the 4 lanes of each row-group
    ps0 += __shfl_xor_sync(0xffffffffu, ps0, 1);
    ps0 += __shfl_xor_sync(0xffffffffu, ps0, 2);
    ps1 += __shfl_xor_sync(0xffffffffu, ps1, 1);
    ps1 += __shfl_xor_sync(0xffffffffu, ps1, 2);
    const float inv0 = 1.0f / ps0, inv1 = 1.0f / ps1;

    const int r0 = l0 + (w << 4) + g;
    float* o0 = g_att + (size_t)(b * NL + r0) * CKD + h * DV + (l << 1);
    float* o1 = o0 + (size_t)8 * CKD;
    #pragma unroll
    for (int j = 0; j < 4; j++) {
        *(float2*)(o0 + (j << 3)) = make_float2(O[j][0] * inv0, O[j][1] * inv0);
        *(float2*)(o1 + (j << 3)) = make_float2(O[j][2] * inv1, O[j][3] * inv1);
    }
}

// ---------------------------------------------------------------------------
// projection GEMM (f32x2): g_y[o][m] = att[m][:256] . Ww[o][:256]
// ---------------------------------------------------------------------------
__global__ __launch_bounds__(256) void gemm_proj_kernel(
    const float* __restrict__ A, const float* __restrict__ W)
{
    __shared__ float As[16][132];
    __shared__ float Bs[16][68];
    const int m0 = blockIdx.x << 7;
    const int c0 = blockIdx.y << 6;
    const int t  = threadIdx.x;
    const int tx = t & 15, ty = t >> 4;
    const int ar = t >> 1, ak = (t & 1) << 3;
    const int bc = t >> 2, bk = (t & 3) << 2;
    u64 acc[4][4] = {};
    for (int k0 = 0; k0 < CKD; k0 += 16) {
        float4 x0 = *(const float4*)&A[(size_t)(m0 + ar) * CKD + k0 + ak];
        float4 x1 = *(const float4*)&A[(size_t)(m0 + ar) * CKD + k0 + ak + 4];
        float4 wv = *(const float4*)&W[(size_t)(c0 + bc) * CKD + k0 + bk];
        __syncthreads();
        As[ak+0][ar]=x0.x; As[ak+1][ar]=x0.y; As[ak+2][ar]=x0.z; As[ak+3][ar]=x0.w;
        As[ak+4][ar]=x1.x; As[ak+5][ar]=x1.y; As[ak+6][ar]=x1.z; As[ak+7][ar]=x1.w;
        Bs[bk+0][bc]=wv.x; Bs[bk+1][bc]=wv.y; Bs[bk+2][bc]=wv.z; Bs[bk+3][bc]=wv.w;
        __syncthreads();
        #pragma unroll
        for (int kk = 0; kk < 16; kk++) {
            float4 a0 = *(const float4*)&As[kk][tx << 2];
            float4 a1 = *(const float4*)&As[kk][64 + (tx << 2)];
            u64 np0 = pk(a0.x, a0.y), np1 = pk(a0.z, a0.w);
            u64 np2 = pk(a1.x, a1.y), np3 = pk(a1.z, a1.w);
            float4 cw = *(const float4*)&Bs[kk][ty << 2];
            u64 w0 = pk(cw.x, cw.x), w1 = pk(cw.y, cw.y);
            u64 w2 = pk(cw.z, cw.z), w3 = pk(cw.w, cw.w);
            acc[0][0]=fma2(np0,w0,acc[0][0]); acc[0][1]=fma2(np1,w0,acc[0][1]);
            acc[0][2]=fma2(np2,w0,acc[0][2]); acc[0][3]=fma2(np3,w0,acc[0][3]);
            acc[1][0]=fma2(np0,w1,acc[1][0]); acc[1][1]=fma2(np1,w1,acc[1][1]);
            acc[1][2]=fma2(np2,w1,acc[1][2]); acc[1][3]=fma2(np3,w1,acc[1][3]);
            acc[2][0]=fma2(np0,w2,acc[2][0]); acc[2][1]=fma2(np1,w2,acc[2][1]);
            acc[2][2]=fma2(np2,w2,acc[2][2]); acc[2][3]=fma2(np3,w2,acc[2][3]);
            acc[3][0]=fma2(np0,w3,acc[3][0]); acc[3][1]=fma2(np1,w3,acc[3][1]);
            acc[3][2]=fma2(np2,w3,acc[3][2]); acc[3][3]=fma2(np3,w3,acc[3][3]);
        }
    }
    #pragma unroll
    for (int i = 0; i < 4; i++) {
        const int cc = c0 + (ty << 2) + i;
        float r0,r1,r2,r3,r4,r5,r6,r7;
        upk(acc[i][0], r0, r1); upk(acc[i][1], r2, r3);
        upk(acc[i][2], r4, r5); upk(acc[i][3], r6, r7);
        float* rp = g_y + (size_t)cc * MTOT + m0 + (tx << 2);
        *(float4*)rp        = make_float4(r0, r1, r2, r3);
        *(float4*)(rp + 64) = make_float4(r4, r5, r6, r7);
    }
}

// ---------------------------------------------------------------------------
// InstanceNorm over Nl on g_y + transposed write out[b,l,o]
// ---------------------------------------------------------------------------
__global__ __launch_bounds__(256) void norm_t_kernel(float* __restrict__ out)
{
    __shared__ float tile[32][33];
    __shared__ float meanv[32], rstdv[32];
    const int b = blockIdx.y, o0 = blockIdx.x << 5;
    const int t = threadIdx.x, lane = t & 31, w = t >> 5;

    #pragma unroll
    for (int j = 0; j < 4; j++) {
        const int ol = (w << 2) + j;
        const float* yp = g_y + (size_t)(o0 + ol) * MTOT + b * NL;
        float s = 0.f, sq = 0.f;
        #pragma unroll
        for (int i = 0; i < 8; i++) {
            float4 v = *(const float4*)&yp[(i * 32 + lane) * 4];
            s  += v.x + v.y + v.z + v.w;
            sq += v.x*v.x + v.y*v.y + v.z*v.z + v.w*v.w;
        }
        #pragma unroll
        for (int off = 16; off; off >>= 1) {
            s  += __shfl_xor_sync(0xffffffffu, s,  off);
            sq += __shfl_xor_sync(0xffffffffu, sq, off);
        }
        if (lane == 0) {
            float mean = s * (1.f / NL);
            float var  = sq * (1.f / NL) - mean * mean;
            meanv[ol] = mean;
            rstdv[ol] = rsqrtf(var + EPSI);
        }
    }
    __syncthreads();
    const float mo = meanv[lane], ro = rstdv[lane];
    for (int l0 = 0; l0 < NL; l0 += 32) {
        __syncthreads();
        #pragma unroll
        for (int j = 0; j < 4; j++)
            tile[w + 8*j][lane] =
                g_y[(size_t)(o0 + w + 8*j) * MTOT + b * NL + l0 + lane];
        __syncthreads();
        #pragma unroll
        for (int j = 0; j < 4; j++)
            out[(size_t)(b * NL + l0 + w + 8*j) * CKD + o0 + lane] =
                (tile[lane][w + 8*j] - mo) * ro;
    }
}

// ---------------------------------------------------------------------------
extern "C" void kernel_launch(void* const* d_in, const int* in_sizes, int n_in,
                              void* d_out, int out_size)
{
    const float* l  = (const float*)d_in[0];
    const float* x  = (const float*)d_in[1];
    const float* Wq = (const float*)d_in[2];
    const float* bq = (const float*)d_in[3];
    const float* Wk = (const float*)d_in[4];
    const float* Wv = (const float*)d_in[6];
    const float* bv = (const float*)d_in[7];
    const float* Ww = (const float*)d_in[8];
    float* out = (float*)d_out;

    float* att; cudaGetSymbolAddress((void**)&att, g_att);

    gemm_q_kernel   <<<dim3(4, 64), 256>>>(l, Wq, bq);
    gemm_kv_kernel  <<<dim3(HWN / 128, 8, BATCH), 256>>>(x, Wk, Wv, bv);
    inorm_k_kernel  <<<BATCH * CKD, 256>>>();
    convert_k_kernel<<<dim3(HWN / 128, NH, BATCH), 256>>>();
    attn_hmma_kernel<<<dim3(NL / 128, NH, BATCH), 256>>>();
    gemm_proj_kernel<<<dim3(32, 4), 256>>>(att, Ww);
    norm_t_kernel   <<<dim3(CKD / 32, BATCH), 256>>>(out);
}

// round 8
// speedup vs baseline: 2.6729x; 1.2213x over previous
#include <cuda_runtime.h>
#include <cuda_fp16.h>
#include <cstdint>

#define BATCH 4
#define NL    1024
#define HWN   4096
#define CIN   512
#define CKD   256
#define NH    8
#define DK    32
#define DV    32
#define MTOT  4096
#define EPSI  1e-5f
#define QSCALE 0.09016844f   /* (1/16) * log2(e) */

typedef unsigned long long u64;

// ---------------- fp32x2 helpers ----------------
__device__ __forceinline__ u64 pk(float a, float b) {
    u64 r;
    asm("mov.b64 %0, {%1, %2};" : "=l"(r)
        : "r"(__float_as_uint(a)), "r"(__float_as_uint(b)));
    return r;
}
__device__ __forceinline__ void upk(u64 p, float& a, float& b) {
    unsigned x, y;
    asm("mov.b64 {%0, %1}, %2;" : "=r"(x), "=r"(y) : "l"(p));
    a = __uint_as_float(x); b = __uint_as_float(y);
}
__device__ __forceinline__ u64 fma2(u64 a, u64 b, u64 c) {
    u64 d;
    asm("fma.rn.f32x2 %0, %1, %2, %3;" : "=l"(d) : "l"(a), "l"(b), "l"(c));
    return d;
}
__device__ __forceinline__ float ex2(float x) {
    float r; asm("ex2.approx.f32 %0, %1;" : "=f"(r) : "f"(x)); return r;
}
__device__ __forceinline__ uint32_t h2pack(float lo, float hi) {
    __half2 h = __floats2half2_rn(lo, hi);     // .x = lo half
    return *(uint32_t*)&h;
}
__device__ __forceinline__ uint32_t smem_u32(const void* p) {
    uint32_t a;
    asm("{ .reg .u64 t; cvta.to.shared.u64 t, %1; cvt.u32.u64 %0, t; }"
        : "=r"(a) : "l"(p));
    return a;
}
__device__ __forceinline__ void ldsm4(uint32_t* r, uint32_t addr) {
    asm volatile("ldmatrix.sync.aligned.m8n8.x4.shared.b16 {%0,%1,%2,%3}, [%4];"
        : "=r"(r[0]), "=r"(r[1]), "=r"(r[2]), "=r"(r[3]) : "r"(addr));
}
__device__ __forceinline__ void mma16816(float* c, const uint32_t* a,
                                         const uint32_t b0, const uint32_t b1) {
    asm volatile(
        "mma.sync.aligned.m16n8k16.row.col.f32.f16.f16.f32 "
        "{%0,%1,%2,%3},{%4,%5,%6,%7},{%8,%9},{%0,%1,%2,%3};"
        : "+f"(c[0]), "+f"(c[1]), "+f"(c[2]), "+f"(c[3])
        : "r"(a[0]), "r"(a[1]), "r"(a[2]), "r"(a[3]), "r"(b0), "r"(b1));
}

// ---------------- scratch ----------------
__device__ __half g_qh[MTOT * CKD];                       // [m][ck] hi, prescaled
__device__ __half g_ql[MTOT * CKD];                       // [m][ck] lo
__device__ __half g_xh[(size_t)BATCH * HWN * CIN];        // x split hi
__device__ __half g_xl[(size_t)BATCH * HWN * CIN];        // x split lo
__device__ __half g_wh[512 * CIN];                        // [Wk;Wv] hi
__device__ __half g_wl[512 * CIN];                        // [Wk;Wv] lo
__device__ float  g_k [(size_t)BATCH * CKD * HWN];        // fp32 [b,c,n]
__device__ __half g_kh[(size_t)BATCH * NH * HWN * DK];    // [b,h][n][dk]
__device__ __half g_vh[(size_t)BATCH * CKD * HWN];        // [b,c,n]
__device__ float  g_att[BATCH * NL * CKD];
__device__ float  g_y[CKD * MTOT];

// ---------------------------------------------------------------------------
// q = (l @ Wq^T + bq) * QSCALE -> fp16 hi/lo
// ---------------------------------------------------------------------------
__global__ __launch_bounds__(256) void gemm_q_kernel(
    const float* __restrict__ L, const float* __restrict__ Wq,
    const float* __restrict__ bq)
{
    __shared__ float As[16][64];
    __shared__ float Bs[16][64];
    const int m0 = blockIdx.y << 6;
    const int c0 = blockIdx.x << 6;
    const int t  = threadIdx.x;
    const int tx = t & 15, ty = t >> 4;
    const int li = t >> 2;
    const int lk = (t & 3) << 2;
    float acc[4][4] = {};
    for (int k0 = 0; k0 < CIN; k0 += 16) {
        float4 a = *(const float4*)&L [(size_t)(m0 + li) * CIN + k0 + lk];
        float4 w = *(const float4*)&Wq[(size_t)(c0 + li) * CIN + k0 + lk];
        __syncthreads();
        As[lk+0][li] = a.x; As[lk+1][li] = a.y; As[lk+2][li] = a.z; As[lk+3][li] = a.w;
        Bs[lk+0][li] = w.x; Bs[lk+1][li] = w.y; Bs[lk+2][li] = w.z; Bs[lk+3][li] = w.w;
        __syncthreads();
        #pragma unroll
        for (int kk = 0; kk < 16; kk++) {
            float4 av = *(const float4*)&As[kk][ty << 2];
            float4 bv = *(const float4*)&Bs[kk][tx << 2];
            float ar[4] = {av.x, av.y, av.z, av.w};
            float br[4] = {bv.x, bv.y, bv.z, bv.w};
            #pragma unroll
            for (int i = 0; i < 4; i++)
                #pragma unroll
                for (int j = 0; j < 4; j++) acc[i][j] += ar[i] * br[j];
        }
    }
    #pragma unroll
    for (int i = 0; i < 4; i++) {
        #pragma unroll
        for (int j = 0; j < 4; j++) {
            float f = (acc[i][j] + bq[c0 + (tx << 2) + j]) * QSCALE;
            __half hi = __float2half_rn(f);
            __half lo = __float2half_rn(f - __half2float(hi));
            size_t idx = (size_t)(m0 + (ty << 2) + i) * CKD + c0 + (tx << 2) + j;
            g_qh[idx] = hi;
            g_ql[idx] = lo;
        }
    }
}

// ---------------------------------------------------------------------------
// split x -> fp16 hi/lo.  grid 4096 x 256 thr, 8 elems each.
// ---------------------------------------------------------------------------
__global__ __launch_bounds__(256) void split_x_kernel(const float* __restrict__ X)
{
    const size_t i0 = ((size_t)blockIdx.x * 256 + threadIdx.x) * 8;
    float4 f0 = *(const float4*)(X + i0);
    float4 f1 = *(const float4*)(X + i0 + 4);
    float f[8] = {f0.x, f0.y, f0.z, f0.w, f1.x, f1.y, f1.z, f1.w};
    uint32_t wh[4], wl[4];
    #pragma unroll
    for (int j = 0; j < 4; j++) {
        float a = f[2*j], b = f[2*j+1];
        __half ha = __float2half_rn(a), hb = __float2half_rn(b);
        wh[j] = h2pack(__half2float(ha), __half2float(hb));
        wl[j] = h2pack(a - __half2float(ha), b - __half2float(hb));
    }
    *(uint2*)(g_xh + i0)     = make_uint2(wh[0], wh[1]);
    *(uint2*)(g_xh + i0 + 4) = make_uint2(wh[2], wh[3]);
    *(uint2*)(g_xl + i0)     = make_uint2(wl[0], wl[1]);
    *(uint2*)(g_xl + i0 + 4) = make_uint2(wl[2], wl[3]);
}

// ---------------------------------------------------------------------------
// split [Wk;Wv] -> fp16 hi/lo.  grid 512 (one row), 256 thr x 2 cols.
// ---------------------------------------------------------------------------
__global__ __launch_bounds__(256) void split_w_kernel(
    const float* __restrict__ Wk, const float* __restrict__ Wv)
{
    const int row = blockIdx.x;
    const float* src = (row < CKD) ? (Wk + (size_t)row * CIN)
                                   : (Wv + (size_t)(row - CKD) * CIN);
    const int c = threadIdx.x * 2;
    float a = src[c], b = src[c + 1];
    __half ha = __float2half_rn(a), hb = __float2half_rn(b);
    *(uint32_t*)(g_wh + (size_t)row * CIN + c) =
        h2pack(__half2float(ha), __half2float(hb));
    *(uint32_t*)(g_wl + (size_t)row * CIN + c) =
        h2pack(a - __half2float(ha), b - __half2float(hb));
}

// ---------------------------------------------------------------------------
// HMMA k/v GEMM, 3-term hi/lo (fp32-accurate).
// M-side = channels (64/group), N-side = n (128/block), K = 512.
// C fragment is [c][n] -> direct transposed stores, no smem epilogue.
// grid (HWN/128, 8, BATCH); groups 0-3 = K channels, 4-7 = V channels.
// ---------------------------------------------------------------------------
__global__ __launch_bounds__(256) void gemm_kv_hmma(const float* __restrict__ bv)
{
    __shared__ __align__(16) __half xhs[128 * 32];
    __shared__ __align__(16) __half xls[128 * 32];
    __shared__ __align__(16) __half whs[64 * 32];
    __shared__ __align__(16) __half wls[64 * 32];

    const int bat = blockIdx.z;
    const int c0  = blockIdx.y << 6;            // 0..448 over [Wk;Wv]
    const int n0  = blockIdx.x << 7;
    const int t = threadIdx.x, w = t >> 5, lane = t & 31;

    // per-thread load coords
    const int xrow = t >> 1, xc2 = (t & 1) << 1;             // x: 2 chunks
    const int wrow = t >> 2, wc = t & 3;                     // w: 1 chunk
    const uint4* pxh = (const uint4*)(g_xh + (size_t)(bat * HWN + n0 + xrow) * CIN);
    const uint4* pxl = (const uint4*)(g_xl + (size_t)(bat * HWN + n0 + xrow) * CIN);
    const uint4* pwh = (const uint4*)(g_wh + (size_t)(c0 + wrow) * CIN);
    const uint4* pwl = (const uint4*)(g_wl + (size_t)(c0 + wrow) * CIN);

    const int cw = (w & 3) << 4;                // warp channel sub-tile (16)
    const int nw = (w >> 2) << 6;               // warp n half (64)
    const uint32_t whb = smem_u32(whs), wlb = smem_u32(wls);
    const uint32_t xhb = smem_u32(xhs), xlb = smem_u32(xls);

    float C[8][4] = {};
    uint4 rxh0, rxh1, rxl0, rxl1, rwh, rwl;
    rxh0 = pxh[xc2]; rxh1 = pxh[xc2 + 1];
    rxl0 = pxl[xc2]; rxl1 = pxl[xc2 + 1];
    rwh  = pwh[wc];  rwl  = pwl[wc];

    for (int s = 0; s < 16; s++) {
        __syncthreads();
        const int xsw = (xrow >> 1) & 3, wsw = (wrow >> 1) & 3;
        ((uint4*)xhs)[xrow * 4 + ((xc2)     ^ xsw)] = rxh0;
        ((uint4*)xhs)[xrow * 4 + ((xc2 + 1) ^ xsw)] = rxh1;
        ((uint4*)xls)[xrow * 4 + ((xc2)     ^ xsw)] = rxl0;
        ((uint4*)xls)[xrow * 4 + ((xc2 + 1) ^ xsw)] = rxl1;
        ((uint4*)whs)[wrow * 4 + (wc ^ wsw)] = rwh;
        ((uint4*)wls)[wrow * 4 + (wc ^ wsw)] = rwl;
        if (s < 15) {
            const int kc = (s + 1) << 2;        // k chunk base (uint4 units)
            rxh0 = pxh[kc + xc2]; rxh1 = pxh[kc + xc2 + 1];
            rxl0 = pxl[kc + xc2]; rxl1 = pxl[kc + xc2 + 1];
            rwh  = pwh[kc + wc];  rwl  = pwl[kc + wc];
        }
        __syncthreads();

        uint32_t Ah[2][4], Al[2][4];
        const int arow = cw + (lane & 7) + ((lane >> 3) & 1) * 8;
        const int aswz = (arow >> 1) & 3;
        #pragma unroll
        for (int ks = 0; ks < 2; ks++) {
            const uint32_t aoff = (arow * 4 + (((ks << 1) + (lane >> 4)) ^ aswz)) * 16;
            ldsm4(Ah[ks], whb + aoff);
            ldsm4(Al[ks], wlb + aoff);
        }
        #pragma unroll
        for (int j = 0; j < 8; j++) {
            const int brow = nw + (j << 3) + (lane & 7);
            const uint32_t boff = (brow * 4 + ((lane >> 3) ^ ((brow >> 1) & 3))) * 16;
            uint32_t bh[4], bl[4];
            ldsm4(bh, xhb + boff);
            ldsm4(bl, xlb + boff);
            mma16816(C[j], Ah[0], bh[0], bh[1]);
            mma16816(C[j], Ah[1], bh[2], bh[3]);
            mma16816(C[j], Ah[0], bl[0], bl[1]);
            mma16816(C[j], Ah[1], bl[2], bl[3]);
            mma16816(C[j], Al[0], bh[0], bh[1]);
            mma16816(C[j], Al[1], bh[2], bh[3]);
        }
    }

    // epilogue: thread (g,l) holds (c = cc, n = 2l) and (c = cc+8)
    const int g = lane >> 2, l = lane & 3;
    const int cc = c0 + cw + g;
    if (c0 < CKD) {           // K channels, no bias (inorm-invariant)
        float* k0p = g_k + ((size_t)bat * CKD + cc) * HWN;
        float* k1p = g_k + ((size_t)bat * CKD + cc + 8) * HWN;
        #pragma unroll
        for (int j = 0; j < 8; j++) {
            const int n = n0 + nw + (j << 3) + (l << 1);
            *(float2*)(k0p + n) = make_float2(C[j][0], C[j][1]);
            *(float2*)(k1p + n) = make_float2(C[j][2], C[j][3]);
        }
    } else {                  // V channels, +bias, fp16
        const int cv = cc - CKD;
        const float b0 = bv[cv], b1 = bv[cv + 8];
        __half* v0p = g_vh + ((size_t)bat * CKD + cv) * HWN;
        __half* v1p = g_vh + ((size_t)bat * CKD + cv + 8) * HWN;
        #pragma unroll
        for (int j = 0; j < 8; j++) {
            const int n = n0 + nw + (j << 3) + (l << 1);
            *(uint32_t*)(v0p + n) = h2pack(C[j][0] + b0, C[j][1] + b0);
            *(uint32_t*)(v1p + n) = h2pack(C[j][2] + b1, C[j][3] + b1);
        }
    }
}

// ---------------------------------------------------------------------------
// InstanceNorm over HW on g_k (fp32, in place)
// ---------------------------------------------------------------------------
__global__ __launch_bounds__(256) void inorm_k_kernel()
{
    __shared__ float red[16];
    const int row = blockIdx.x;
    float4* p4 = reinterpret_cast<float4*>(g_k + (size_t)row * HWN);
    const int t = threadIdx.x;
    float4 v[4];
    float s = 0.f, sq = 0.f;
    #pragma unroll
    for (int i = 0; i < 4; i++) {
        v[i] = p4[t + 256 * i];
        s  += v[i].x + v[i].y + v[i].z + v[i].w;
        sq += v[i].x * v[i].x + v[i].y * v[i].y + v[i].z * v[i].z + v[i].w * v[i].w;
    }
    #pragma unroll
    for (int off = 16; off; off >>= 1) {
        s  += __shfl_xor_sync(0xffffffffu, s,  off);
        sq += __shfl_xor_sync(0xffffffffu, sq, off);
    }
    if ((t & 31) == 0) { red[t >> 5] = s; red[8 + (t >> 5)] = sq; }
    __syncthreads();
    if (t == 0) {
        float S = 0.f, Q = 0.f;
        #pragma unroll
        for (int i = 0; i < 8; i++) { S += red[i]; Q += red[8 + i]; }
        float mean = S * (1.f / HWN);
        float var  = Q * (1.f / HWN) - mean * mean;
        red[0] = mean;
        red[1] = rsqrtf(var + EPSI);
    }
    __syncthreads();
    const float mean = red[0], rstd = red[1];
    #pragma unroll
    for (int i = 0; i < 4; i++) {
        v[i].x = (v[i].x - mean) * rstd;
        v[i].y = (v[i].y - mean) * rstd;
        v[i].z = (v[i].z - mean) * rstd;
        v[i].w = (v[i].w - mean) * rstd;
        p4[t + 256 * i] = v[i];
    }
}

// ---------------------------------------------------------------------------
// Transpose normalized K -> g_kh [b,h][n][dk] fp16
// ---------------------------------------------------------------------------
__global__ __launch_bounds__(256) void convert_k_kernel()
{
    __shared__ float tile[32][132];
    const int b = blockIdx.z, h = blockIdx.y, n0 = blockIdx.x << 7;
    const int t = threadIdx.x;
    {
        const int dk = t >> 3, seg = (t & 7) << 4;
        const float* src = g_k + ((size_t)b * CKD + h * DK + dk) * HWN + n0 + seg;
        #pragma unroll
        for (int u = 0; u < 4; u++) {
            float4 v = *(const float4*)(src + 4 * u);
            tile[dk][seg + 4*u + 0] = v.x;
            tile[dk][seg + 4*u + 1] = v.y;
            tile[dk][seg + 4*u + 2] = v.z;
            tile[dk][seg + 4*u + 3] = v.w;
        }
    }
    __syncthreads();
    const int n = t >> 1, part = t & 1;
    uint32_t w[8];
    #pragma unroll
    for (int j = 0; j < 8; j++)
        w[j] = h2pack(tile[part*16 + 2*j][n], tile[part*16 + 2*j + 1][n]);
    __half* dst = g_kh + ((size_t)(b * NH + h) * HWN + n0 + n) * DK + part * 16;
    ((uint4*)dst)[0] = make_uint4(w[0], w[1], w[2], w[3]);
    ((uint4*)dst)[1] = make_uint4(w[4], w[5], w[6], w[7]);
}

// ---------------------------------------------------------------------------
// HMMA attention (unchanged from R7)
// ---------------------------------------------------------------------------
__global__ __launch_bounds__(256) void attn_hmma_kernel()
{
    __shared__ __align__(16) __half qs_h[128 * 32];
    __shared__ __align__(16) __half qs_l[128 * 32];
    __shared__ __align__(16) __half ks[64 * 32];
    __shared__ __align__(16) __half vsm[32 * 64];

    const int b = blockIdx.z, h = blockIdx.y, l0 = blockIdx.x << 7;
    const int t = threadIdx.x, w = t >> 5, lane = t & 31;
    const int g = lane >> 2, l = lane & 3;

    {
        const int row = t >> 1, cp = (t & 1) << 1;
        const uint4* srch = (const uint4*)(g_qh + (size_t)(b * NL + l0 + row) * CKD + h * DK);
        const uint4* srcl = (const uint4*)(g_ql + (size_t)(b * NL + l0 + row) * CKD + h * DK);
        const int sw = (row >> 1) & 3;
        ((uint4*)qs_h)[row * 4 + (cp ^ sw)]       = srch[cp];
        ((uint4*)qs_h)[row * 4 + ((cp + 1) ^ sw)] = srch[cp + 1];
        ((uint4*)qs_l)[row * 4 + (cp ^ sw)]       = srcl[cp];
        ((uint4*)qs_l)[row * 4 + ((cp + 1) ^ sw)] = srcl[cp + 1];
    }
    __syncthreads();

    uint32_t Ah[2][4], Al[2][4];
    {
        const int row = (w << 4) + (lane & 7) + ((lane >> 3) & 1) * 8;
        const int kc  = lane >> 4;
        const int sw  = (row >> 1) & 3;
        #pragma unroll
        for (int s = 0; s < 2; s++) {
            const uint32_t off = (row * 4 + (((s << 1) + kc) ^ sw)) * 16;
            ldsm4(Ah[s], smem_u32(qs_h) + off);
            ldsm4(Al[s], smem_u32(qs_l) + off);
        }
    }

    const __half* kg = g_kh + (size_t)(b * NH + h) * HWN * DK;
    const __half* vg = g_vh + ((size_t)b * CKD + h * DV) * HWN;
    const uint32_t ksb = smem_u32(ks), vsb = smem_u32(vsm);

    const int krow = t >> 2, kck = t & 3;
    const int vrow = t >> 3, vck = t & 7;
    const uint4* kg4 = (const uint4*)kg;
    const uint4* vg4 = (const uint4*)vg;
    uint4 krv = kg4[krow * 4 + kck];
    uint4 vrv = vg4[(size_t)vrow * (HWN / 8) + vck];

    float O[4][4] = {};
    float ps0 = 0.f, ps1 = 0.f;

    for (int c = 0; c < 64; c++) {
        __syncthreads();
        ((uint4*)ks)[krow * 4 + (kck ^ ((krow >> 1) & 3))] = krv;
        ((uint4*)vsm)[vrow * 8 + (vck ^ (vrow & 7))]       = vrv;
        if (c < 63) {
            krv = kg4[((c + 1) * 64 + krow) * 4 + kck];
            vrv = vg4[(size_t)vrow * (HWN / 8) + (c + 1) * 8 + vck];
        }
        __syncthreads();

        float S[8][4];
        #pragma unroll
        for (int j = 0; j < 8; j++) { S[j][0]=0.f; S[j][1]=0.f; S[j][2]=0.f; S[j][3]=0.f; }
        #pragma unroll
        for (int j = 0; j < 8; j++) {
            const int row = (j << 3) + (lane & 7);
            uint32_t bk_[4];
            ldsm4(bk_, ksb + (row * 4 + ((lane >> 3) ^ ((row >> 1) & 3))) * 16);
            mma16816(S[j], Ah[0], bk_[0], bk_[1]);
            mma16816(S[j], Ah[1], bk_[2], bk_[3]);
            mma16816(S[j], Al[0], bk_[0], bk_[1]);
            mma16816(S[j], Al[1], bk_[2], bk_[3]);
        }

        uint32_t Ph[4][4];
        #pragma unroll
        for (int j = 0; j < 8; j++) {
            float p0 = ex2(S[j][0]), p1 = ex2(S[j][1]);
            float p2 = ex2(S[j][2]), p3 = ex2(S[j][3]);
            ps0 += p0 + p1;
            ps1 += p2 + p3;
            Ph[j >> 1][(j & 1) * 2 + 0] = h2pack(p0, p1);
            Ph[j >> 1][(j & 1) * 2 + 1] = h2pack(p2, p3);
        }

        #pragma unroll
        for (int j = 0; j < 4; j++) {
            #pragma unroll
            for (int s2 = 0; s2 < 2; s2++) {
                const int row = (j << 3) + (lane & 7);
                uint32_t bv_[4];
                ldsm4(bv_, vsb + (row * 8 + (((s2 << 2) + (lane >> 3)) ^ (row & 7))) * 16);
                mma16816(O[j], Ph[2 * s2],     bv_[0], bv_[1]);
                mma16816(O[j], Ph[2 * s2 + 1], bv_[2], bv_[3]);
            }
        }
    }

    ps0 += __shfl_xor_sync(0xffffffffu, ps0, 1);
    ps0 += __shfl_xor_sync(0xffffffffu, ps0, 2);
    ps1 += __shfl_xor_sync(0xffffffffu, ps1, 1);
    ps1 += __shfl_xor_sync(0xffffffffu, ps1, 2);
    const float inv0 = 1.0f / ps0, inv1 = 1.0f / ps1;

    const int r0 = l0 + (w << 4) + g;
    float* o0 = g_att + (size_t)(b * NL + r0) * CKD + h * DV + (l << 1);
    float* o1 = o0 + (size_t)8 * CKD;
    #pragma unroll
    for (int j = 0; j < 4; j++) {
        *(float2*)(o0 + (j << 3)) = make_float2(O[j][0] * inv0, O[j][1] * inv0);
        *(float2*)(o1 + (j << 3)) = make_float2(O[j][2] * inv1, O[j][3] * inv1);
    }
}

// ---------------------------------------------------------------------------
// projection GEMM (f32x2): g_y[o][m] = att[m][:256] . Ww[o][:256]
// ---------------------------------------------------------------------------
__global__ __launch_bounds__(256) void gemm_proj_kernel(
    const float* __restrict__ A, const float* __restrict__ W)
{
    __shared__ float As[16][132];
    __shared__ float Bs[16][68];
    const int m0 = blockIdx.x << 7;
    const int c0 = blockIdx.y << 6;
    const int t  = threadIdx.x;
    const int tx = t & 15, ty = t >> 4;
    const int ar = t >> 1, ak = (t & 1) << 3;
    const int bc = t >> 2, bk = (t & 3) << 2;
    u64 acc[4][4] = {};
    for (int k0 = 0; k0 < CKD; k0 += 16) {
        float4 x0 = *(const float4*)&A[(size_t)(m0 + ar) * CKD + k0 + ak];
        float4 x1 = *(const float4*)&A[(size_t)(m0 + ar) * CKD + k0 + ak + 4];
        float4 wv = *(const float4*)&W[(size_t)(c0 + bc) * CKD + k0 + bk];
        __syncthreads();
        As[ak+0][ar]=x0.x; As[ak+1][ar]=x0.y; As[ak+2][ar]=x0.z; As[ak+3][ar]=x0.w;
        As[ak+4][ar]=x1.x; As[ak+5][ar]=x1.y; As[ak+6][ar]=x1.z; As[ak+7][ar]=x1.w;
        Bs[bk+0][bc]=wv.x; Bs[bk+1][bc]=wv.y; Bs[bk+2][bc]=wv.z; Bs[bk+3][bc]=wv.w;
        __syncthreads();
        #pragma unroll
        for (int kk = 0; kk < 16; kk++) {
            float4 a0 = *(const float4*)&As[kk][tx << 2];
            float4 a1 = *(const float4*)&As[kk][64 + (tx << 2)];
            u64 np0 = pk(a0.x, a0.y), np1 = pk(a0.z, a0.w);
            u64 np2 = pk(a1.x, a1.y), np3 = pk(a1.z, a1.w);
            float4 cw = *(const float4*)&Bs[kk][ty << 2];
            u64 w0 = pk(cw.x, cw.x), w1 = pk(cw.y, cw.y);
            u64 w2 = pk(cw.z, cw.z), w3 = pk(cw.w, cw.w);
            acc[0][0]=fma2(np0,w0,acc[0][0]); acc[0][1]=fma2(np1,w0,acc[0][1]);
            acc[0][2]=fma2(np2,w0,acc[0][2]); acc[0][3]=fma2(np3,w0,acc[0][3]);
            acc[1][0]=fma2(np0,w1,acc[1][0]); acc[1][1]=fma2(np1,w1,acc[1][1]);
            acc[1][2]=fma2(np2,w1,acc[1][2]); acc[1][3]=fma2(np3,w1,acc[1][3]);
            acc[2][0]=fma2(np0,w2,acc[2][0]); acc[2][1]=fma2(np1,w2,acc[2][1]);
            acc[2][2]=fma2(np2,w2,acc[2][2]); acc[2][3]=fma2(np3,w2,acc[2][3]);
            acc[3][0]=fma2(np0,w3,acc[3][0]); acc[3][1]=fma2(np1,w3,acc[3][1]);
            acc[3][2]=fma2(np2,w3,acc[3][2]); acc[3][3]=fma2(np3,w3,acc[3][3]);
        }
    }
    #pragma unroll
    for (int i = 0; i < 4; i++) {
        const int cc = c0 + (ty << 2) + i;
        float r0,r1,r2,r3,r4,r5,r6,r7;
        upk(acc[i][0], r0, r1); upk(acc[i][1], r2, r3);
        upk(acc[i][2], r4, r5); upk(acc[i][3], r6, r7);
        float* rp = g_y + (size_t)cc * MTOT + m0 + (tx << 2);
        *(float4*)rp        = make_float4(r0, r1, r2, r3);
        *(float4*)(rp + 64) = make_float4(r4, r5, r6, r7);
    }
}

// ---------------------------------------------------------------------------
// InstanceNorm over Nl on g_y + transposed write out[b,l,o]
// ---------------------------------------------------------------------------
__global__ __launch_bounds__(256) void norm_t_kernel(float* __restrict__ out)
{
    __shared__ float tile[32][33];
    __shared__ float meanv[32], rstdv[32];
    const int b = blockIdx.y, o0 = blockIdx.x << 5;
    const int t = threadIdx.x, lane = t & 31, w = t >> 5;

    #pragma unroll
    for (int j = 0; j < 4; j++) {
        const int ol = (w << 2) + j;
        const float* yp = g_y + (size_t)(o0 + ol) * MTOT + b * NL;
        float s = 0.f, sq = 0.f;
        #pragma unroll
        for (int i = 0; i < 8; i++) {
            float4 v = *(const float4*)&yp[(i * 32 + lane) * 4];
            s  += v.x + v.y + v.z + v.w;
            sq += v.x*v.x + v.y*v.y + v.z*v.z + v.w*v.w;
        }
        #pragma unroll
        for (int off = 16; off; off >>= 1) {
            s  += __shfl_xor_sync(0xffffffffu, s,  off);
            sq += __shfl_xor_sync(0xffffffffu, sq, off);
        }
        if (lane == 0) {
            float mean = s * (1.f / NL);
            float var  = sq * (1.f / NL) - mean * mean;
            meanv[ol] = mean;
            rstdv[ol] = rsqrtf(var + EPSI);
        }
    }
    __syncthreads();
    const float mo = meanv[lane], ro = rstdv[lane];
    for (int l0 = 0; l0 < NL; l0 += 32) {
        __syncthreads();
        #pragma unroll
        for (int j = 0; j < 4; j++)
            tile[w + 8*j][lane] =
                g_y[(size_t)(o0 + w + 8*j) * MTOT + b * NL + l0 + lane];
        __syncthreads();
        #pragma unroll
        for (int j = 0; j < 4; j++)
            out[(size_t)(b * NL + l0 + w + 8*j) * CKD + o0 + lane] =
                (tile[lane][w + 8*j] - mo) * ro;
    }
}

// ---------------------------------------------------------------------------
extern "C" void kernel_launch(void* const* d_in, const int* in_sizes, int n_in,
                              void* d_out, int out_size)
{
    const float* l  = (const float*)d_in[0];
    const float* x  = (const float*)d_in[1];
    const float* Wq = (const float*)d_in[2];
    const float* bq = (const float*)d_in[3];
    const float* Wk = (const float*)d_in[4];
    const float* Wv = (const float*)d_in[6];
    const float* bv = (const float*)d_in[7];
    const float* Ww = (const float*)d_in[8];
    float* out = (float*)d_out;

    float* att; cudaGetSymbolAddress((void**)&att, g_att);

    split_w_kernel  <<<512, 256>>>(Wk, Wv);
    split_x_kernel  <<<(BATCH * HWN * CIN) / (256 * 8), 256>>>(x);
    gemm_q_kernel   <<<dim3(4, 64), 256>>>(l, Wq, bq);
    gemm_kv_hmma    <<<dim3(HWN / 128, 8, BATCH), 256>>>(bv);
    inorm_k_kernel  <<<BATCH * CKD, 256>>>();
    convert_k_kernel<<<dim3(HWN / 128, NH, BATCH), 256>>>();
    attn_hmma_kernel<<<dim3(NL / 128, NH, BATCH), 256>>>();
    gemm_proj_kernel<<<dim3(32, 4), 256>>>(att, Ww);
    norm_t_kernel   <<<dim3(CKD / 32, BATCH), 256>>>(out);
}